// round 13
// baseline (speedup 1.0000x reference)
#include <cuda_runtime.h>
#include <cuda_bf16.h>
#include <math.h>
#include <stdint.h>

#define B_    256
#define S_    512
#define F_    128
#define H_    64
#define G_    192
#define C_    100
#define KTOT  32768
#define SPLITK 32
#define KCHUNK 1024      // KTOT/SPLITK
#define NKB   (KCHUNK / 64)

// ---------------- scratch (device globals; no allocation allowed) ----------
__device__ float          g_gx[131072 * 192];
__device__ __nv_bfloat16  g_xhi[131072 * 128];
__device__ __nv_bfloat16  g_xlo[131072 * 128];
__device__ __nv_bfloat16  g_wxhi[192 * 128];
__device__ __nv_bfloat16  g_wxlo[192 * 128];
__device__ __nv_bfloat16  g_hhi[256 * 32768];
__device__ __nv_bfloat16  g_hlo[256 * 32768];
__device__ __nv_bfloat16  g_w1hi[512 * 32768];
__device__ __nv_bfloat16  g_w1lo[512 * 32768];
__device__ float          g_hst[256 * 64];
__device__ float          g_fc1p[SPLITK * 256 * 512];
__device__ float          g_fc1[256 * 512];
__device__ float          g_fc2[256 * 256];

// ---------------- helpers ----------------------------------------------------
__device__ __forceinline__ uint32_t smem_u32(const void* p) {
    uint32_t a;
    asm("{ .reg .u64 t; cvta.to.shared.u64 t, %1; cvt.u32.u64 %0, t; }" : "=r"(a) : "l"(p));
    return a;
}
__device__ __forceinline__ void ldm4(uint32_t* r, uint32_t addr) {
    asm volatile("ldmatrix.sync.aligned.m8n8.x4.shared.b16 {%0,%1,%2,%3}, [%4];"
        : "=r"(r[0]), "=r"(r[1]), "=r"(r[2]), "=r"(r[3]) : "r"(addr));
}
#define MMA(c, a, b0, b1) \
    asm volatile("mma.sync.aligned.m16n8k16.row.col.f32.bf16.bf16.f32 " \
        "{%0,%1,%2,%3}, {%4,%5,%6,%7}, {%8,%9}, {%0,%1,%2,%3};" \
        : "+f"((c)[0]), "+f"((c)[1]), "+f"((c)[2]), "+f"((c)[3]) \
        : "r"((a)[0]), "r"((a)[1]), "r"((a)[2]), "r"((a)[3]), "r"(b0), "r"(b1))

#define CP16(dst, src) asm volatile("cp.async.cg.shared.global [%0], [%1], 16;" :: "r"(dst), "l"(src))
#define CPCOMMIT()     asm volatile("cp.async.commit_group;" ::: "memory")
#define CPWAIT(n)      asm volatile("cp.async.wait_group %0;" :: "n"(n) : "memory")

typedef unsigned long long u64;
__device__ __forceinline__ u64 pack2f(float lo, float hi) {
    u64 r; asm("mov.b64 %0, {%1, %2};" : "=l"(r) : "f"(lo), "f"(hi)); return r;
}
__device__ __forceinline__ u64 ffma2(u64 a, u64 b, u64 c) {
    u64 d; asm("fma.rn.f32x2 %0, %1, %2, %3;" : "=l"(d) : "l"(a), "l"(b), "l"(c)); return d;
}
__device__ __forceinline__ u64 fadd2(u64 a, u64 b) {
    u64 d; asm("add.rn.f32x2 %0, %1, %2;" : "=l"(d) : "l"(a), "l"(b)); return d;
}
__device__ __forceinline__ float2 unpack2(u64 v) {
    float2 f; asm("mov.b64 {%0, %1}, %2;" : "=f"(f.x), "=f"(f.y) : "l"(v)); return f;
}

__device__ __forceinline__ uint32_t packbf2(float a, float b) {
    __nv_bfloat162 t = __floats2bfloat162_rn(a, b);
    return *reinterpret_cast<uint32_t*>(&t);
}
__device__ __forceinline__ void split2(float a, float b, uint32_t& hi, uint32_t& lo) {
    __nv_bfloat16 ha = __float2bfloat16(a), hb = __float2bfloat16(b);
    __nv_bfloat162 h; h.x = ha; h.y = hb;
    hi = *reinterpret_cast<uint32_t*>(&h);
    lo = packbf2(a - __bfloat162float(ha), b - __bfloat162float(hb));
}

#define SA 72
#define ROWB 144

// ========== generic fp32 -> bf16 hi/lo streaming convert ====================
__global__ __launch_bounds__(256) void cvt_split(
    const float* __restrict__ src, __nv_bfloat16* __restrict__ hi, __nv_bfloat16* __restrict__ lo)
{
    size_t i = (size_t)blockIdx.x * 256 + threadIdx.x;
    float4 v = ((const float4*)src)[i];
    uint32_t h01, l01, h23, l23;
    split2(v.x, v.y, h01, l01);
    split2(v.z, v.w, h23, l23);
    *(uint2*)(hi + 4 * i) = make_uint2(h01, h23);
    *(uint2*)(lo + 4 * i) = make_uint2(l01, l23);
}

// ===== gx = x @ Wx^T (all-bf16 cp.async double-buffered, K=128) =============
#define GXP_AHI 0
#define GXP_ALO 18432
#define GXP_BHI 36864
#define GXP_BLO 64512
#define GXP_STG 92160
#define GX_SMEM (2 * GXP_STG)

__global__ __launch_bounds__(384, 1) void gx_mma(
    const __nv_bfloat16* __restrict__ Ahi_g, const __nv_bfloat16* __restrict__ Alo_g,
    const __nv_bfloat16* __restrict__ Bhi_g, const __nv_bfloat16* __restrict__ Blo_g,
    float* __restrict__ gx)
{
    extern __shared__ __align__(16) char sm[];
    const uint32_t sb = smem_u32(sm);
    const int tid = threadIdx.x;
    const int lane = tid & 31, wid = tid >> 5;
    const int wm = wid & 3, wn = wid >> 2;
    const int row0 = blockIdx.x * 128;

    float acc[2][8][4] = {};

    const uint32_t a_frag = (uint32_t)(wm * 32 + (lane & 15)) * ROWB + ((lane >> 4) * 16);
    const uint32_t b_frag = (uint32_t)(wn * 64 + ((lane >> 4) << 3) + (lane & 7)) * ROWB
                            + ((lane & 8) ? 16 : 0);

    auto load_stage = [&](int stg, int kbase) {
        const uint32_t base = sb + (uint32_t)stg * GXP_STG;
        for (int idx = tid; idx < 1024; idx += 384) {
            int r = idx >> 3, c8 = idx & 7;
            size_t go = (size_t)(row0 + r) * F_ + kbase + c8 * 8;
            uint32_t d = base + (uint32_t)(r * ROWB + c8 * 16);
            CP16(d + GXP_AHI, Ahi_g + go);
            CP16(d + GXP_ALO, Alo_g + go);
        }
        #pragma unroll
        for (int i = 0; i < 4; i++) {
            int idx = i * 384 + tid;
            int r = idx >> 3, c8 = idx & 7;
            size_t go = (size_t)r * F_ + kbase + c8 * 8;
            uint32_t d = base + (uint32_t)(r * ROWB + c8 * 16);
            CP16(d + GXP_BHI, Bhi_g + go);
            CP16(d + GXP_BLO, Blo_g + go);
        }
        CPCOMMIT();
    };

    load_stage(0, 0);
    load_stage(1, 64);

    for (int kb = 0; kb < 2; kb++) {
        if (kb == 0) { CPWAIT(1); } else { CPWAIT(0); }
        __syncthreads();

        const uint32_t stg = sb + (uint32_t)kb * GXP_STG;
        const uint32_t a_base = stg + GXP_AHI + a_frag;
        const uint32_t b_base = stg + GXP_BHI + b_frag;

        #pragma unroll
        for (int kk = 0; kk < 64; kk += 16) {
            uint32_t ah[2][4], al[2][4];
            ldm4(ah[0], a_base + kk * 2);
            ldm4(ah[1], a_base + 2304 + kk * 2);
            ldm4(al[0], a_base + (GXP_ALO - GXP_AHI) + kk * 2);
            ldm4(al[1], a_base + (GXP_ALO - GXP_AHI) + 2304 + kk * 2);
            #pragma unroll
            for (int nt = 0; nt < 4; nt++) {
                uint32_t bh[4], bl[4];
                ldm4(bh, b_base + nt * 2304 + kk * 2);
                ldm4(bl, b_base + (GXP_BLO - GXP_BHI) + nt * 2304 + kk * 2);
                #pragma unroll
                for (int mt = 0; mt < 2; mt++) {
                    MMA(acc[mt][nt * 2 + 0], ah[mt], bh[0], bh[1]);
                    MMA(acc[mt][nt * 2 + 1], ah[mt], bh[2], bh[3]);
                    MMA(acc[mt][nt * 2 + 0], ah[mt], bl[0], bl[1]);
                    MMA(acc[mt][nt * 2 + 1], ah[mt], bl[2], bl[3]);
                    MMA(acc[mt][nt * 2 + 0], al[mt], bh[0], bh[1]);
                    MMA(acc[mt][nt * 2 + 1], al[mt], bh[2], bh[3]);
                }
            }
        }
    }

    const int g = lane >> 2, tq = lane & 3;
    #pragma unroll
    for (int mt = 0; mt < 2; mt++) {
        #pragma unroll
        for (int n8 = 0; n8 < 8; n8++) {
            int row = row0 + wm * 32 + mt * 16 + g;
            int col = wn * 64 + n8 * 8 + tq * 2;
            *(float2*)&gx[(size_t)row * G_ + col]       = make_float2(acc[mt][n8][0], acc[mt][n8][1]);
            *(float2*)&gx[(size_t)(row + 8) * G_ + col] = make_float2(acc[mt][n8][2], acc[mt][n8][3]);
        }
    }
}

// ===== fc1 = hout @ W1^T (all-bf16 cp.async pipelined, split-K=32) ==========
// Launched in 4 z-groups of 8 chunks; group with zbase z0 depends only on
// GRU timesteps < 16*(z0+8).
#define F1_AHI 0
#define F1_ALO 18432
#define F1_BHI 36864
#define F1_BLO 55296
#define F1_STG 73728
#define FC1_SMEM (2 * F1_STG)

__global__ __launch_bounds__(256, 1) void fc1_mma(
    const __nv_bfloat16* __restrict__ Ahi_g, const __nv_bfloat16* __restrict__ Alo_g,
    const __nv_bfloat16* __restrict__ Bhi_g, const __nv_bfloat16* __restrict__ Blo_g,
    float* __restrict__ part, int zbase)
{
    extern __shared__ __align__(16) char sm[];
    const uint32_t sb = smem_u32(sm);
    const int tid = threadIdx.x;
    const int lane = tid & 31, wid = tid >> 5;
    const int wm = wid & 3, wn = wid >> 2;
    const int row0 = blockIdx.y * 128;
    const int col0 = blockIdx.x * 128;
    const int z = zbase + blockIdx.z;
    const int k0 = z * KCHUNK;

    float acc[2][8][4] = {};

    const uint32_t a_frag = (uint32_t)(wm * 32 + (lane & 15)) * ROWB + ((lane >> 4) * 16);
    const uint32_t b_frag = (uint32_t)(wn * 64 + ((lane >> 4) << 3) + (lane & 7)) * ROWB
                            + ((lane & 8) ? 16 : 0);

    auto load_stage = [&](int stg, int kbase) {
        const uint32_t base = sb + (uint32_t)stg * F1_STG;
        #pragma unroll
        for (int i = 0; i < 4; i++) {
            int idx = i * 256 + tid;
            int r = idx >> 3, c8 = idx & 7;
            size_t go = (size_t)(row0 + r) * KTOT + kbase + c8 * 8;
            uint32_t d = base + (uint32_t)(r * ROWB + c8 * 16);
            CP16(d + F1_AHI, Ahi_g + go);
            CP16(d + F1_ALO, Alo_g + go);
        }
        #pragma unroll
        for (int i = 0; i < 4; i++) {
            int idx = i * 256 + tid;
            int r = idx >> 3, c8 = idx & 7;
            size_t go = (size_t)(col0 + r) * KTOT + kbase + c8 * 8;
            uint32_t d = base + (uint32_t)(r * ROWB + c8 * 16);
            CP16(d + F1_BHI, Bhi_g + go);
            CP16(d + F1_BLO, Blo_g + go);
        }
        CPCOMMIT();
    };

    load_stage(0, k0);

    for (int kb = 0; kb < NKB; kb++) {
        if (kb + 1 < NKB) load_stage((kb + 1) & 1, k0 + (kb + 1) * 64);
        if (kb + 1 < NKB) { CPWAIT(1); } else { CPWAIT(0); }
        __syncthreads();

        const uint32_t stg = sb + (uint32_t)(kb & 1) * F1_STG;
        const uint32_t a_base = stg + F1_AHI + a_frag;
        const uint32_t b_base = stg + F1_BHI + b_frag;

        #pragma unroll
        for (int kk = 0; kk < 64; kk += 16) {
            uint32_t ah[2][4], al[2][4];
            ldm4(ah[0], a_base + kk * 2);
            ldm4(ah[1], a_base + 2304 + kk * 2);
            ldm4(al[0], a_base + (F1_ALO - F1_AHI) + kk * 2);
            ldm4(al[1], a_base + (F1_ALO - F1_AHI) + 2304 + kk * 2);
            #pragma unroll
            for (int nt = 0; nt < 4; nt++) {
                uint32_t bh[4], bl[4];
                ldm4(bh, b_base + nt * 2304 + kk * 2);
                ldm4(bl, b_base + (F1_BLO - F1_BHI) + nt * 2304 + kk * 2);
                #pragma unroll
                for (int mt = 0; mt < 2; mt++) {
                    MMA(acc[mt][nt * 2 + 0], ah[mt], bh[0], bh[1]);
                    MMA(acc[mt][nt * 2 + 1], ah[mt], bh[2], bh[3]);
                    MMA(acc[mt][nt * 2 + 0], ah[mt], bl[0], bl[1]);
                    MMA(acc[mt][nt * 2 + 1], ah[mt], bl[2], bl[3]);
                    MMA(acc[mt][nt * 2 + 0], al[mt], bh[0], bh[1]);
                    MMA(acc[mt][nt * 2 + 1], al[mt], bh[2], bh[3]);
                }
            }
        }
        __syncthreads();
    }

    const int g = lane >> 2, tq = lane & 3;
    const size_t obase = (size_t)z * 256 * 512;
    #pragma unroll
    for (int mt = 0; mt < 2; mt++) {
        #pragma unroll
        for (int n8 = 0; n8 < 8; n8++) {
            int row = row0 + wm * 32 + mt * 16 + g;
            int col = col0 + wn * 64 + n8 * 8 + tq * 2;
            *(float2*)&part[obase + (size_t)row * 512 + col]       = make_float2(acc[mt][n8][0], acc[mt][n8][1]);
            *(float2*)&part[obase + (size_t)(row + 8) * 512 + col] = make_float2(acc[mt][n8][2], acc[mt][n8][3]);
        }
    }
}

// ---------------- split-K reduce -------------------------------------------
__global__ __launch_bounds__(256) void reduce_fc1(
    const float* __restrict__ p, float* __restrict__ o)
{
    int i = blockIdx.x * 256 + threadIdx.x;
    const float4* p4 = (const float4*)p;
    float4 s = make_float4(0.f, 0.f, 0.f, 0.f);
    #pragma unroll
    for (int sk = 0; sk < SPLITK; sk++) {
        float4 v = p4[(size_t)sk * 32768 + i];
        s.x += v.x; s.y += v.y; s.z += v.z; s.w += v.w;
    }
    ((float4*)o)[i] = s;
}

// ---------------- fp32 gemm (fc2 only) -------------------------------------
template <int BM, int BN, int TM, int TN, bool RELU_A>
__global__ __launch_bounds__(256) void gemm2(
    const float* __restrict__ A, const float* __restrict__ Bm, float* __restrict__ C,
    int M, int N, int K)
{
    __shared__ float As[16][BM];
    __shared__ float Bs[16][BN];
    const int row0 = blockIdx.y * BM;
    const int col0 = blockIdx.x * BN;
    const int tid = threadIdx.x;
    const int tx = tid & 15, ty = tid >> 4;
    const int lrow = tid >> 2, lk = (tid & 3) * 4;

    float acc[TM][TN] = {};
    for (int k = 0; k < K; k += 16) {
        #pragma unroll
        for (int j = 0; j < BM / 64; j++) {
            int r = j * 64 + lrow;
            float4 v = *(const float4*)&A[(size_t)(row0 + r) * K + k + lk];
            if (RELU_A) {
                v.x = fmaxf(v.x, 0.f); v.y = fmaxf(v.y, 0.f);
                v.z = fmaxf(v.z, 0.f); v.w = fmaxf(v.w, 0.f);
            }
            As[lk + 0][r] = v.x; As[lk + 1][r] = v.y;
            As[lk + 2][r] = v.z; As[lk + 3][r] = v.w;
        }
        #pragma unroll
        for (int j = 0; j < BN / 64; j++) {
            int r = j * 64 + lrow;
            float4 v = *(const float4*)&Bm[(size_t)(col0 + r) * K + k + lk];
            Bs[lk + 0][r] = v.x; Bs[lk + 1][r] = v.y;
            Bs[lk + 2][r] = v.z; Bs[lk + 3][r] = v.w;
        }
        __syncthreads();
        #pragma unroll
        for (int kk = 0; kk < 16; kk++) {
            float a[TM], b[TN];
            #pragma unroll
            for (int i = 0; i < TM; i++) a[i] = As[kk][ty * TM + i];
            #pragma unroll
            for (int j = 0; j < TN; j++) b[j] = Bs[kk][tx * TN + j];
            #pragma unroll
            for (int i = 0; i < TM; i++)
                #pragma unroll
                for (int j = 0; j < TN; j++) acc[i][j] += a[i] * b[j];
        }
        __syncthreads();
    }
    #pragma unroll
    for (int i = 0; i < TM; i++)
        #pragma unroll
        for (int j = 0; j < TN; j++)
            C[(size_t)(row0 + ty * TM + i) * N + col0 + tx * TN + j] = acc[i][j];
}

// ===== GRU quarters, v3 config: 128 blocks x 256 thr, 2 chains/block ========
__device__ __forceinline__ float fast_sigmoid(float x) {
    return __fdividef(1.0f, 1.0f + __expf(-x));
}
__device__ __forceinline__ float fast_tanh(float x) {
    return 1.0f - __fdividef(2.0f, __expf(2.0f * x) + 1.0f);
}
#define BARG(id) asm volatile("bar.sync %0, 128;" :: "r"(id) : "memory")

__global__ __launch_bounds__(256) void gru_scan(
    const float* __restrict__ gx, const float* __restrict__ W_h2h,
    __nv_bfloat16* __restrict__ hhi, __nv_bfloat16* __restrict__ hlo,
    float* __restrict__ hst, int s_begin, int s_end)
{
    const int g = threadIdx.x >> 7;
    const int t = threadIdx.x & 127;
    const int u = t >> 1;
    const int half = t & 1;
    const int b = blockIdx.x * 2 + g;
    const int barid = 1 + g;

    __shared__ __align__(16) float sh[2][2][H_];

    u64 w2r[16], w2z[16], w2n[16];
    {
        const float* wr = W_h2h + (size_t)u * H_ + half * 32;
        const float* wz = W_h2h + (size_t)(64 + u) * H_ + half * 32;
        const float* wn = W_h2h + (size_t)(128 + u) * H_ + half * 32;
        #pragma unroll
        for (int j = 0; j < 16; j++) {
            float2 a = *(const float2*)(wr + 2 * j); w2r[j] = pack2f(a.x, a.y);
            float2 bz = *(const float2*)(wz + 2 * j); w2z[j] = pack2f(bz.x, bz.y);
            float2 cn = *(const float2*)(wn + 2 * j); w2n[j] = pack2f(cn.x, cn.y);
        }
    }

    float hinit = (s_begin > 0) ? hst[b * H_ + u] : 0.f;
    if (half == 0) sh[0][g][u] = hinit;
    __syncthreads();

    const size_t base = (size_t)b * S_ * G_;
    float pir[4], pii[4], pin[4];
    if (half == 0) {
        #pragma unroll
        for (int d = 0; d < 4; d++) {
            size_t o = base + (size_t)(s_begin + d) * G_;
            pir[d] = gx[o + u];
            pii[d] = gx[o + 64 + u];
            pin[d] = gx[o + 128 + u];
        }
    }

    float hprev = hinit;

    for (int s4 = s_begin; s4 < s_end; s4 += 4) {
        #pragma unroll
        for (int ph = 0; ph < 4; ph++) {
            const int s = s4 + ph;
            const int cur = ph & 1;
            const int nxt = cur ^ 1;

            const u64* hp = (const u64*)&sh[cur][g][half * 32];
            u64 ar0 = 0ull, ar1 = 0ull, az0 = 0ull, az1 = 0ull, an0 = 0ull, an1 = 0ull;
            #pragma unroll
            for (int j = 0; j < 16; j += 2) {
                u64 h0 = hp[j], h1 = hp[j + 1];
                ar0 = ffma2(w2r[j], h0, ar0); ar1 = ffma2(w2r[j + 1], h1, ar1);
                az0 = ffma2(w2z[j], h0, az0); az1 = ffma2(w2z[j + 1], h1, az1);
                an0 = ffma2(w2n[j], h0, an0); an1 = ffma2(w2n[j + 1], h1, an1);
            }
            float2 fr = unpack2(fadd2(ar0, ar1));
            float2 fz = unpack2(fadd2(az0, az1));
            float2 fn = unpack2(fadd2(an0, an1));
            float rdot = fr.x + fr.y;
            float zdot = fz.x + fz.y;
            float ndot = fn.x + fn.y;
            rdot += __shfl_xor_sync(0xffffffffu, rdot, 1);
            zdot += __shfl_xor_sync(0xffffffffu, zdot, 1);
            ndot += __shfl_xor_sync(0xffffffffu, ndot, 1);

            if (half == 0) {
                float r = fast_sigmoid(pir[ph] + rdot);
                float z = fast_sigmoid(pii[ph] + zdot);
                float n = fast_tanh(pin[ph] + r * ndot);
                float hn = n + z * (hprev - n);
                hprev = hn;
                sh[nxt][g][u] = hn;
                size_t idx = ((size_t)b * S_ + s) * H_ + u;
                __nv_bfloat16 hb = __float2bfloat16(hn);
                hhi[idx] = hb;
                hlo[idx] = __float2bfloat16(hn - __bfloat162float(hb));
                if (s + 4 < s_end) {
                    size_t nb = base + (size_t)(s + 4) * G_;
                    pir[ph] = gx[nb + u];
                    pii[ph] = gx[nb + 64 + u];
                    pin[ph] = gx[nb + 128 + u];
                }
            }
            BARG(barid);
        }
    }

    if (half == 0 && s_end < S_) hst[b * H_ + u] = hprev;
}

// ---------------- fc3 + softmax --------------------------------------------
__global__ __launch_bounds__(128) void fc3_softmax(
    const float* __restrict__ fc2, const float* __restrict__ W3,
    float* __restrict__ out)
{
    const int b = blockIdx.x;
    const int t = threadIdx.x;
    __shared__ float sa[256];
    __shared__ float slog[C_];
    __shared__ float red[128];

    for (int k = t; k < 256; k += 128) sa[k] = fmaxf(fc2[b * 256 + k], 0.f);
    __syncthreads();

    float acc = 0.f;
    if (t < C_) {
        const float* wr = &W3[t * 256];
        #pragma unroll 8
        for (int k = 0; k < 256; k++) acc += sa[k] * wr[k];
        slog[t] = acc;
    }
    __syncthreads();

    float m = -1e30f;
    for (int k = t; k < C_; k += 128) m = fmaxf(m, slog[k]);
    red[t] = m; __syncthreads();
    for (int st = 64; st > 0; st >>= 1) {
        if (t < st) red[t] = fmaxf(red[t], red[t + st]);
        __syncthreads();
    }
    float mx = red[0];
    __syncthreads();

    float e = 0.f;
    if (t < C_) { e = __expf(slog[t] - mx); slog[t] = e; }
    red[t] = (t < C_) ? e : 0.f; __syncthreads();
    for (int st = 64; st > 0; st >>= 1) {
        if (t < st) red[t] += red[t + st];
        __syncthreads();
    }
    float inv = 1.0f / red[0];
    __syncthreads();

    if (t < C_) out[b * C_ + t] = slog[t] * inv;
}

// ---------------- launch ----------------------------------------------------
extern "C" void kernel_launch(void* const* d_in, const int* in_sizes, int n_in,
                              void* d_out, int out_size)
{
    const float* x     = (const float*)d_in[0];
    const float* W_x2h = (const float*)d_in[1];
    const float* W_h2h = (const float*)d_in[2];
    const float* W1    = (const float*)d_in[3];
    const float* W2    = (const float*)d_in[4];
    const float* W3    = (const float*)d_in[5];
    float* out = (float*)d_out;

    float *gx, *hst, *fc1p, *fc1, *fc2;
    __nv_bfloat16 *xhi, *xlo, *wxhi, *wxlo, *hhi, *hlo, *w1hi, *w1lo;
    cudaGetSymbolAddress((void**)&gx,   g_gx);
    cudaGetSymbolAddress((void**)&xhi,  g_xhi);
    cudaGetSymbolAddress((void**)&xlo,  g_xlo);
    cudaGetSymbolAddress((void**)&wxhi, g_wxhi);
    cudaGetSymbolAddress((void**)&wxlo, g_wxlo);
    cudaGetSymbolAddress((void**)&hhi,  g_hhi);
    cudaGetSymbolAddress((void**)&hlo,  g_hlo);
    cudaGetSymbolAddress((void**)&w1hi, g_w1hi);
    cudaGetSymbolAddress((void**)&w1lo, g_w1lo);
    cudaGetSymbolAddress((void**)&hst,  g_hst);
    cudaGetSymbolAddress((void**)&fc1p, g_fc1p);
    cudaGetSymbolAddress((void**)&fc1,  g_fc1);
    cudaGetSymbolAddress((void**)&fc2,  g_fc2);

    cudaFuncSetAttribute(gx_mma,  cudaFuncAttributeMaxDynamicSharedMemorySize, GX_SMEM);
    cudaFuncSetAttribute(fc1_mma, cudaFuncAttributeMaxDynamicSharedMemorySize, FC1_SMEM);

    // side stream + events (host-side objects only; capture-legal)
    cudaStream_t sB;
    cudaStreamCreateWithFlags(&sB, cudaStreamNonBlocking);
    cudaEvent_t evF, eq0, eq1, eq2, evJ;
    cudaEventCreateWithFlags(&evF, cudaEventDisableTiming);
    cudaEventCreateWithFlags(&eq0, cudaEventDisableTiming);
    cudaEventCreateWithFlags(&eq1, cudaEventDisableTiming);
    cudaEventCreateWithFlags(&eq2, cudaEventDisableTiming);
    cudaEventCreateWithFlags(&evJ, cudaEventDisableTiming);

    cudaEventRecord(evF, 0);
    cudaStreamWaitEvent(sB, evF, 0);

    // main: converts + gx + GRU quarter 1 (profiled slot 4)
    cvt_split<<<16384, 256>>>(x, xhi, xlo);
    cvt_split<<<24, 256>>>(W_x2h, wxhi, wxlo);
    gx_mma<<<1024, 384, GX_SMEM>>>(xhi, xlo, wxhi, wxlo, gx);
    gru_scan<<<128, 256>>>(gx, W_h2h, hhi, hlo, hst, 0, 128);
    cudaEventRecord(eq0, 0);

    // side: W1 convert from t=0, then fc1 group 1 after GRU q1
    cvt_split<<<16384, 256, 0, sB>>>(W1, w1hi, w1lo);
    cudaStreamWaitEvent(sB, eq0, 0);
    fc1_mma<<<dim3(4, 2, 8), 256, FC1_SMEM, sB>>>(hhi, hlo, w1hi, w1lo, fc1p, 0);

    // main: GRU q2; side: fc1 group 2
    gru_scan<<<128, 256>>>(gx, W_h2h, hhi, hlo, hst, 128, 256);
    cudaEventRecord(eq1, 0);
    cudaStreamWaitEvent(sB, eq1, 0);
    fc1_mma<<<dim3(4, 2, 8), 256, FC1_SMEM, sB>>>(hhi, hlo, w1hi, w1lo, fc1p, 8);

    // main: GRU q3; side: fc1 group 3
    gru_scan<<<128, 256>>>(gx, W_h2h, hhi, hlo, hst, 256, 384);
    cudaEventRecord(eq2, 0);
    cudaStreamWaitEvent(sB, eq2, 0);
    fc1_mma<<<dim3(4, 2, 8), 256, FC1_SMEM, sB>>>(hhi, hlo, w1hi, w1lo, fc1p, 16);
    cudaEventRecord(evJ, sB);

    // main: GRU q4, join side, fc1 group 4
    gru_scan<<<128, 256>>>(gx, W_h2h, hhi, hlo, hst, 384, 512);
    cudaStreamWaitEvent(0, evJ, 0);
    fc1_mma<<<dim3(4, 2, 8), 256, FC1_SMEM>>>(hhi, hlo, w1hi, w1lo, fc1p, 24);

    // tail
    reduce_fc1<<<128, 256>>>(fc1p, fc1);
    {
        dim3 grid(256 / 64, B_ / 64);
        gemm2<64, 64, 4, 4, true><<<grid, 256>>>(fc1, W2, fc2, B_, 256, 512);
    }
    fc3_softmax<<<B_, 128>>>(fc2, W3, out);
}

// round 14
// speedup vs baseline: 1.1043x; 1.1043x over previous
#include <cuda_runtime.h>
#include <cuda_bf16.h>
#include <math.h>
#include <stdint.h>

#define B_    256
#define S_    512
#define F_    128
#define H_    64
#define G_    192
#define C_    100
#define KTOT  32768
#define SPLITK 16
#define KCHUNK 2048      // KTOT/SPLITK
#define NKB   (KCHUNK / 64)

// ---------------- scratch (device globals; no allocation allowed) ----------
__device__ float          g_gx[131072 * 192];
__device__ __nv_bfloat16  g_xhi[131072 * 128];
__device__ __nv_bfloat16  g_xlo[131072 * 128];
__device__ __nv_bfloat16  g_wxhi[192 * 128];
__device__ __nv_bfloat16  g_wxlo[192 * 128];
__device__ __nv_bfloat16  g_hhi[256 * 32768];
__device__ __nv_bfloat16  g_hlo[256 * 32768];
__device__ __nv_bfloat16  g_w1hi[512 * 32768];
__device__ __nv_bfloat16  g_w1lo[512 * 32768];
__device__ float          g_fc1p[SPLITK * 256 * 512];
__device__ float          g_fc1[256 * 512];
__device__ float          g_fc2[256 * 256];

// ---------------- helpers ----------------------------------------------------
__device__ __forceinline__ uint32_t smem_u32(const void* p) {
    uint32_t a;
    asm("{ .reg .u64 t; cvta.to.shared.u64 t, %1; cvt.u32.u64 %0, t; }" : "=r"(a) : "l"(p));
    return a;
}
__device__ __forceinline__ void ldm4(uint32_t* r, uint32_t addr) {
    asm volatile("ldmatrix.sync.aligned.m8n8.x4.shared.b16 {%0,%1,%2,%3}, [%4];"
        : "=r"(r[0]), "=r"(r[1]), "=r"(r[2]), "=r"(r[3]) : "r"(addr));
}
#define MMA(c, a, b0, b1) \
    asm volatile("mma.sync.aligned.m16n8k16.row.col.f32.bf16.bf16.f32 " \
        "{%0,%1,%2,%3}, {%4,%5,%6,%7}, {%8,%9}, {%0,%1,%2,%3};" \
        : "+f"((c)[0]), "+f"((c)[1]), "+f"((c)[2]), "+f"((c)[3]) \
        : "r"((a)[0]), "r"((a)[1]), "r"((a)[2]), "r"((a)[3]), "r"(b0), "r"(b1))

#define CP16(dst, src) asm volatile("cp.async.cg.shared.global [%0], [%1], 16;" :: "r"(dst), "l"(src))
#define CPCOMMIT()     asm volatile("cp.async.commit_group;" ::: "memory")
#define CPWAIT(n)      asm volatile("cp.async.wait_group %0;" :: "n"(n) : "memory")

typedef unsigned long long u64;
__device__ __forceinline__ u64 pack2f(float lo, float hi) {
    u64 r; asm("mov.b64 %0, {%1, %2};" : "=l"(r) : "f"(lo), "f"(hi)); return r;
}
__device__ __forceinline__ u64 ffma2(u64 a, u64 b, u64 c) {
    u64 d; asm("fma.rn.f32x2 %0, %1, %2, %3;" : "=l"(d) : "l"(a), "l"(b), "l"(c)); return d;
}
__device__ __forceinline__ u64 fadd2(u64 a, u64 b) {
    u64 d; asm("add.rn.f32x2 %0, %1, %2;" : "=l"(d) : "l"(a), "l"(b)); return d;
}
__device__ __forceinline__ float2 unpack2(u64 v) {
    float2 f; asm("mov.b64 {%0, %1}, %2;" : "=f"(f.x), "=f"(f.y) : "l"(v)); return f;
}

__device__ __forceinline__ uint32_t packbf2(float a, float b) {
    __nv_bfloat162 t = __floats2bfloat162_rn(a, b);
    return *reinterpret_cast<uint32_t*>(&t);
}
__device__ __forceinline__ void split2(float a, float b, uint32_t& hi, uint32_t& lo) {
    __nv_bfloat16 ha = __float2bfloat16(a), hb = __float2bfloat16(b);
    __nv_bfloat162 h; h.x = ha; h.y = hb;
    hi = *reinterpret_cast<uint32_t*>(&h);
    lo = packbf2(a - __bfloat162float(ha), b - __bfloat162float(hb));
}

#define SA 72
#define ROWB 144

// ========== generic fp32 -> bf16 hi/lo streaming convert ====================
__global__ __launch_bounds__(256) void cvt_split(
    const float* __restrict__ src, __nv_bfloat16* __restrict__ hi, __nv_bfloat16* __restrict__ lo)
{
    size_t i = (size_t)blockIdx.x * 256 + threadIdx.x;
    float4 v = ((const float4*)src)[i];
    uint32_t h01, l01, h23, l23;
    split2(v.x, v.y, h01, l01);
    split2(v.z, v.w, h23, l23);
    *(uint2*)(hi + 4 * i) = make_uint2(h01, h23);
    *(uint2*)(lo + 4 * i) = make_uint2(l01, l23);
}

// ===== gx = x @ Wx^T (all-bf16 cp.async double-buffered, K=128) =============
#define GXP_AHI 0
#define GXP_ALO 18432
#define GXP_BHI 36864
#define GXP_BLO 64512
#define GXP_STG 92160
#define GX_SMEM (2 * GXP_STG)

__global__ __launch_bounds__(384, 1) void gx_mma(
    const __nv_bfloat16* __restrict__ Ahi_g, const __nv_bfloat16* __restrict__ Alo_g,
    const __nv_bfloat16* __restrict__ Bhi_g, const __nv_bfloat16* __restrict__ Blo_g,
    float* __restrict__ gx)
{
    extern __shared__ __align__(16) char sm[];
    const uint32_t sb = smem_u32(sm);
    const int tid = threadIdx.x;
    const int lane = tid & 31, wid = tid >> 5;
    const int wm = wid & 3, wn = wid >> 2;
    const int row0 = blockIdx.x * 128;

    float acc[2][8][4] = {};

    const uint32_t a_frag = (uint32_t)(wm * 32 + (lane & 15)) * ROWB + ((lane >> 4) * 16);
    const uint32_t b_frag = (uint32_t)(wn * 64 + ((lane >> 4) << 3) + (lane & 7)) * ROWB
                            + ((lane & 8) ? 16 : 0);

    auto load_stage = [&](int stg, int kbase) {
        const uint32_t base = sb + (uint32_t)stg * GXP_STG;
        for (int idx = tid; idx < 1024; idx += 384) {
            int r = idx >> 3, c8 = idx & 7;
            size_t go = (size_t)(row0 + r) * F_ + kbase + c8 * 8;
            uint32_t d = base + (uint32_t)(r * ROWB + c8 * 16);
            CP16(d + GXP_AHI, Ahi_g + go);
            CP16(d + GXP_ALO, Alo_g + go);
        }
        #pragma unroll
        for (int i = 0; i < 4; i++) {
            int idx = i * 384 + tid;
            int r = idx >> 3, c8 = idx & 7;
            size_t go = (size_t)r * F_ + kbase + c8 * 8;
            uint32_t d = base + (uint32_t)(r * ROWB + c8 * 16);
            CP16(d + GXP_BHI, Bhi_g + go);
            CP16(d + GXP_BLO, Blo_g + go);
        }
        CPCOMMIT();
    };

    load_stage(0, 0);
    load_stage(1, 64);

    for (int kb = 0; kb < 2; kb++) {
        if (kb == 0) { CPWAIT(1); } else { CPWAIT(0); }
        __syncthreads();

        const uint32_t stg = sb + (uint32_t)kb * GXP_STG;
        const uint32_t a_base = stg + GXP_AHI + a_frag;
        const uint32_t b_base = stg + GXP_BHI + b_frag;

        #pragma unroll
        for (int kk = 0; kk < 64; kk += 16) {
            uint32_t ah[2][4], al[2][4];
            ldm4(ah[0], a_base + kk * 2);
            ldm4(ah[1], a_base + 2304 + kk * 2);
            ldm4(al[0], a_base + (GXP_ALO - GXP_AHI) + kk * 2);
            ldm4(al[1], a_base + (GXP_ALO - GXP_AHI) + 2304 + kk * 2);
            #pragma unroll
            for (int nt = 0; nt < 4; nt++) {
                uint32_t bh[4], bl[4];
                ldm4(bh, b_base + nt * 2304 + kk * 2);
                ldm4(bl, b_base + (GXP_BLO - GXP_BHI) + nt * 2304 + kk * 2);
                #pragma unroll
                for (int mt = 0; mt < 2; mt++) {
                    MMA(acc[mt][nt * 2 + 0], ah[mt], bh[0], bh[1]);
                    MMA(acc[mt][nt * 2 + 1], ah[mt], bh[2], bh[3]);
                    MMA(acc[mt][nt * 2 + 0], ah[mt], bl[0], bl[1]);
                    MMA(acc[mt][nt * 2 + 1], ah[mt], bl[2], bl[3]);
                    MMA(acc[mt][nt * 2 + 0], al[mt], bh[0], bh[1]);
                    MMA(acc[mt][nt * 2 + 1], al[mt], bh[2], bh[3]);
                }
            }
        }
    }

    const int g = lane >> 2, tq = lane & 3;
    #pragma unroll
    for (int mt = 0; mt < 2; mt++) {
        #pragma unroll
        for (int n8 = 0; n8 < 8; n8++) {
            int row = row0 + wm * 32 + mt * 16 + g;
            int col = wn * 64 + n8 * 8 + tq * 2;
            *(float2*)&gx[(size_t)row * G_ + col]       = make_float2(acc[mt][n8][0], acc[mt][n8][1]);
            *(float2*)&gx[(size_t)(row + 8) * G_ + col] = make_float2(acc[mt][n8][2], acc[mt][n8][3]);
        }
    }
}

// ===== fc1 = hout @ W1^T (all-bf16 cp.async TRIPLE-buffered, split-K=16) ====
#define F1_AHI 0
#define F1_ALO 18432
#define F1_BHI 36864
#define F1_BLO 55296
#define F1_STG 73728
#define FC1_SMEM (3 * F1_STG)

__global__ __launch_bounds__(256, 1) void fc1_mma(
    const __nv_bfloat16* __restrict__ Ahi_g, const __nv_bfloat16* __restrict__ Alo_g,
    const __nv_bfloat16* __restrict__ Bhi_g, const __nv_bfloat16* __restrict__ Blo_g,
    float* __restrict__ part)
{
    extern __shared__ __align__(16) char sm[];
    const uint32_t sb = smem_u32(sm);
    const int tid = threadIdx.x;
    const int lane = tid & 31, wid = tid >> 5;
    const int wm = wid & 3, wn = wid >> 2;
    const int row0 = blockIdx.y * 128;
    const int col0 = blockIdx.x * 128;
    const int k0 = blockIdx.z * KCHUNK;

    float acc[2][8][4] = {};

    const uint32_t a_frag = (uint32_t)(wm * 32 + (lane & 15)) * ROWB + ((lane >> 4) * 16);
    const uint32_t b_frag = (uint32_t)(wn * 64 + ((lane >> 4) << 3) + (lane & 7)) * ROWB
                            + ((lane & 8) ? 16 : 0);

    auto load_stage = [&](int stg, int kbase) {
        const uint32_t base = sb + (uint32_t)stg * F1_STG;
        #pragma unroll
        for (int i = 0; i < 4; i++) {
            int idx = i * 256 + tid;
            int r = idx >> 3, c8 = idx & 7;
            size_t go = (size_t)(row0 + r) * KTOT + kbase + c8 * 8;
            uint32_t d = base + (uint32_t)(r * ROWB + c8 * 16);
            CP16(d + F1_AHI, Ahi_g + go);
            CP16(d + F1_ALO, Alo_g + go);
        }
        #pragma unroll
        for (int i = 0; i < 4; i++) {
            int idx = i * 256 + tid;
            int r = idx >> 3, c8 = idx & 7;
            size_t go = (size_t)(col0 + r) * KTOT + kbase + c8 * 8;
            uint32_t d = base + (uint32_t)(r * ROWB + c8 * 16);
            CP16(d + F1_BHI, Bhi_g + go);
            CP16(d + F1_BLO, Blo_g + go);
        }
        CPCOMMIT();
    };

    // 3-stage pipeline: stages 0,1 in flight before the loop.
    load_stage(0, k0);
    load_stage(1, k0 + 64);

    for (int kb = 0; kb < NKB; kb++) {
        if (kb + 1 < NKB) { CPWAIT(1); } else { CPWAIT(0); }
        __syncthreads();
        // stage (kb+2)%3 == (kb-1)%3, freed by the sync above
        if (kb + 2 < NKB) load_stage((kb + 2) % 3, k0 + (kb + 2) * 64);

        const uint32_t stg = sb + (uint32_t)(kb % 3) * F1_STG;
        const uint32_t a_base = stg + F1_AHI + a_frag;
        const uint32_t b_base = stg + F1_BHI + b_frag;

        #pragma unroll
        for (int kk = 0; kk < 64; kk += 16) {
            uint32_t ah[2][4], al[2][4];
            ldm4(ah[0], a_base + kk * 2);
            ldm4(ah[1], a_base + 2304 + kk * 2);
            ldm4(al[0], a_base + (F1_ALO - F1_AHI) + kk * 2);
            ldm4(al[1], a_base + (F1_ALO - F1_AHI) + 2304 + kk * 2);
            #pragma unroll
            for (int nt = 0; nt < 4; nt++) {
                uint32_t bh[4], bl[4];
                ldm4(bh, b_base + nt * 2304 + kk * 2);
                ldm4(bl, b_base + (F1_BLO - F1_BHI) + nt * 2304 + kk * 2);
                #pragma unroll
                for (int mt = 0; mt < 2; mt++) {
                    MMA(acc[mt][nt * 2 + 0], ah[mt], bh[0], bh[1]);
                    MMA(acc[mt][nt * 2 + 1], ah[mt], bh[2], bh[3]);
                    MMA(acc[mt][nt * 2 + 0], ah[mt], bl[0], bl[1]);
                    MMA(acc[mt][nt * 2 + 1], ah[mt], bl[2], bl[3]);
                    MMA(acc[mt][nt * 2 + 0], al[mt], bh[0], bh[1]);
                    MMA(acc[mt][nt * 2 + 1], al[mt], bh[2], bh[3]);
                }
            }
        }
    }

    const int g = lane >> 2, tq = lane & 3;
    const size_t obase = (size_t)blockIdx.z * 256 * 512;
    #pragma unroll
    for (int mt = 0; mt < 2; mt++) {
        #pragma unroll
        for (int n8 = 0; n8 < 8; n8++) {
            int row = row0 + wm * 32 + mt * 16 + g;
            int col = col0 + wn * 64 + n8 * 8 + tq * 2;
            *(float2*)&part[obase + (size_t)row * 512 + col]       = make_float2(acc[mt][n8][0], acc[mt][n8][1]);
            *(float2*)&part[obase + (size_t)(row + 8) * 512 + col] = make_float2(acc[mt][n8][2], acc[mt][n8][3]);
        }
    }
}

// ---------------- split-K reduce -------------------------------------------
__global__ __launch_bounds__(256) void reduce_fc1(
    const float* __restrict__ p, float* __restrict__ o)
{
    int i = blockIdx.x * 256 + threadIdx.x;
    const float4* p4 = (const float4*)p;
    float4 s = make_float4(0.f, 0.f, 0.f, 0.f);
    #pragma unroll
    for (int sk = 0; sk < SPLITK; sk++) {
        float4 v = p4[(size_t)sk * 32768 + i];
        s.x += v.x; s.y += v.y; s.z += v.z; s.w += v.w;
    }
    ((float4*)o)[i] = s;
}

// ---------------- fp32 gemm (fc2 only) -------------------------------------
template <int BM, int BN, int TM, int TN, bool RELU_A>
__global__ __launch_bounds__(256) void gemm2(
    const float* __restrict__ A, const float* __restrict__ Bm, float* __restrict__ C,
    int M, int N, int K)
{
    __shared__ float As[16][BM];
    __shared__ float Bs[16][BN];
    const int row0 = blockIdx.y * BM;
    const int col0 = blockIdx.x * BN;
    const int tid = threadIdx.x;
    const int tx = tid & 15, ty = tid >> 4;
    const int lrow = tid >> 2, lk = (tid & 3) * 4;

    float acc[TM][TN] = {};
    for (int k = 0; k < K; k += 16) {
        #pragma unroll
        for (int j = 0; j < BM / 64; j++) {
            int r = j * 64 + lrow;
            float4 v = *(const float4*)&A[(size_t)(row0 + r) * K + k + lk];
            if (RELU_A) {
                v.x = fmaxf(v.x, 0.f); v.y = fmaxf(v.y, 0.f);
                v.z = fmaxf(v.z, 0.f); v.w = fmaxf(v.w, 0.f);
            }
            As[lk + 0][r] = v.x; As[lk + 1][r] = v.y;
            As[lk + 2][r] = v.z; As[lk + 3][r] = v.w;
        }
        #pragma unroll
        for (int j = 0; j < BN / 64; j++) {
            int r = j * 64 + lrow;
            float4 v = *(const float4*)&Bm[(size_t)(col0 + r) * K + k + lk];
            Bs[lk + 0][r] = v.x; Bs[lk + 1][r] = v.y;
            Bs[lk + 2][r] = v.z; Bs[lk + 3][r] = v.w;
        }
        __syncthreads();
        #pragma unroll
        for (int kk = 0; kk < 16; kk++) {
            float a[TM], b[TN];
            #pragma unroll
            for (int i = 0; i < TM; i++) a[i] = As[kk][ty * TM + i];
            #pragma unroll
            for (int j = 0; j < TN; j++) b[j] = Bs[kk][tx * TN + j];
            #pragma unroll
            for (int i = 0; i < TM; i++)
                #pragma unroll
                for (int j = 0; j < TN; j++) acc[i][j] += a[i] * b[j];
        }
        __syncthreads();
    }
    #pragma unroll
    for (int i = 0; i < TM; i++)
        #pragma unroll
        for (int j = 0; j < TN; j++)
            C[(size_t)(row0 + ty * TM + i) * N + col0 + tx * TN + j] = acc[i][j];
}

// ========== GRU v3 (R8/R11-best: 2 thr/unit, shfl, 1 named bar/step) ========
__device__ __forceinline__ float fast_sigmoid(float x) {
    return __fdividef(1.0f, 1.0f + __expf(-x));
}
__device__ __forceinline__ float fast_tanh(float x) {
    return 1.0f - __fdividef(2.0f, __expf(2.0f * x) + 1.0f);
}
#define BARG(id) asm volatile("bar.sync %0, 128;" :: "r"(id) : "memory")

__global__ __launch_bounds__(256) void gru_scan(
    const float* __restrict__ gx, const float* __restrict__ W_h2h,
    __nv_bfloat16* __restrict__ hhi, __nv_bfloat16* __restrict__ hlo)
{
    const int g = threadIdx.x >> 7;
    const int t = threadIdx.x & 127;
    const int u = t >> 1;
    const int half = t & 1;
    const int b = blockIdx.x * 2 + g;
    const int barid = 1 + g;

    __shared__ __align__(16) float sh[2][2][H_];

    u64 w2r[16], w2z[16], w2n[16];
    {
        const float* wr = W_h2h + (size_t)u * H_ + half * 32;
        const float* wz = W_h2h + (size_t)(64 + u) * H_ + half * 32;
        const float* wn = W_h2h + (size_t)(128 + u) * H_ + half * 32;
        #pragma unroll
        for (int j = 0; j < 16; j++) {
            float2 a = *(const float2*)(wr + 2 * j); w2r[j] = pack2f(a.x, a.y);
            float2 bz = *(const float2*)(wz + 2 * j); w2z[j] = pack2f(bz.x, bz.y);
            float2 cn = *(const float2*)(wn + 2 * j); w2n[j] = pack2f(cn.x, cn.y);
        }
    }

    if (half == 0) sh[0][g][u] = 0.f;
    __syncthreads();

    const size_t base = (size_t)b * S_ * G_;
    float pir[4], pii[4], pin[4];
    if (half == 0) {
        #pragma unroll
        for (int d = 0; d < 4; d++) {
            size_t o = base + (size_t)d * G_;
            pir[d] = gx[o + u];
            pii[d] = gx[o + 64 + u];
            pin[d] = gx[o + 128 + u];
        }
    }

    float hprev = 0.f;

    for (int s4 = 0; s4 < S_; s4 += 4) {
        #pragma unroll
        for (int ph = 0; ph < 4; ph++) {
            const int s = s4 + ph;
            const int cur = ph & 1;
            const int nxt = cur ^ 1;

            const u64* hp = (const u64*)&sh[cur][g][half * 32];
            u64 ar0 = 0ull, ar1 = 0ull, az0 = 0ull, az1 = 0ull, an0 = 0ull, an1 = 0ull;
            #pragma unroll
            for (int j = 0; j < 16; j += 2) {
                u64 h0 = hp[j], h1 = hp[j + 1];
                ar0 = ffma2(w2r[j], h0, ar0); ar1 = ffma2(w2r[j + 1], h1, ar1);
                az0 = ffma2(w2z[j], h0, az0); az1 = ffma2(w2z[j + 1], h1, az1);
                an0 = ffma2(w2n[j], h0, an0); an1 = ffma2(w2n[j + 1], h1, an1);
            }
            float2 fr = unpack2(fadd2(ar0, ar1));
            float2 fz = unpack2(fadd2(az0, az1));
            float2 fn = unpack2(fadd2(an0, an1));
            float rdot = fr.x + fr.y;
            float zdot = fz.x + fz.y;
            float ndot = fn.x + fn.y;
            rdot += __shfl_xor_sync(0xffffffffu, rdot, 1);
            zdot += __shfl_xor_sync(0xffffffffu, zdot, 1);
            ndot += __shfl_xor_sync(0xffffffffu, ndot, 1);

            if (half == 0) {
                float r = fast_sigmoid(pir[ph] + rdot);
                float z = fast_sigmoid(pii[ph] + zdot);
                float n = fast_tanh(pin[ph] + r * ndot);
                float hn = n + z * (hprev - n);
                hprev = hn;
                sh[nxt][g][u] = hn;
                size_t idx = ((size_t)b * S_ + s) * H_ + u;
                __nv_bfloat16 hb = __float2bfloat16(hn);
                hhi[idx] = hb;
                hlo[idx] = __float2bfloat16(hn - __bfloat162float(hb));
                if (s + 4 < S_) {
                    size_t nb = base + (size_t)(s + 4) * G_;
                    pir[ph] = gx[nb + u];
                    pii[ph] = gx[nb + 64 + u];
                    pin[ph] = gx[nb + 128 + u];
                }
            }
            BARG(barid);
        }
    }
}

// ---------------- fc3 + softmax --------------------------------------------
__global__ __launch_bounds__(128) void fc3_softmax(
    const float* __restrict__ fc2, const float* __restrict__ W3,
    float* __restrict__ out)
{
    const int b = blockIdx.x;
    const int t = threadIdx.x;
    __shared__ float sa[256];
    __shared__ float slog[C_];
    __shared__ float red[128];

    for (int k = t; k < 256; k += 128) sa[k] = fmaxf(fc2[b * 256 + k], 0.f);
    __syncthreads();

    float acc = 0.f;
    if (t < C_) {
        const float* wr = &W3[t * 256];
        #pragma unroll 8
        for (int k = 0; k < 256; k++) acc += sa[k] * wr[k];
        slog[t] = acc;
    }
    __syncthreads();

    float m = -1e30f;
    for (int k = t; k < C_; k += 128) m = fmaxf(m, slog[k]);
    red[t] = m; __syncthreads();
    for (int st = 64; st > 0; st >>= 1) {
        if (t < st) red[t] = fmaxf(red[t], red[t + st]);
        __syncthreads();
    }
    float mx = red[0];
    __syncthreads();

    float e = 0.f;
    if (t < C_) { e = __expf(slog[t] - mx); slog[t] = e; }
    red[t] = (t < C_) ? e : 0.f; __syncthreads();
    for (int st = 64; st > 0; st >>= 1) {
        if (t < st) red[t] += red[t + st];
        __syncthreads();
    }
    float inv = 1.0f / red[0];
    __syncthreads();

    if (t < C_) out[b * C_ + t] = slog[t] * inv;
}

// ---------------- launch ----------------------------------------------------
extern "C" void kernel_launch(void* const* d_in, const int* in_sizes, int n_in,
                              void* d_out, int out_size)
{
    const float* x     = (const float*)d_in[0];
    const float* W_x2h = (const float*)d_in[1];
    const float* W_h2h = (const float*)d_in[2];
    const float* W1    = (const float*)d_in[3];
    const float* W2    = (const float*)d_in[4];
    const float* W3    = (const float*)d_in[5];
    float* out = (float*)d_out;

    float *gx, *fc1p, *fc1, *fc2;
    __nv_bfloat16 *xhi, *xlo, *wxhi, *wxlo, *hhi, *hlo, *w1hi, *w1lo;
    cudaGetSymbolAddress((void**)&gx,   g_gx);
    cudaGetSymbolAddress((void**)&xhi,  g_xhi);
    cudaGetSymbolAddress((void**)&xlo,  g_xlo);
    cudaGetSymbolAddress((void**)&wxhi, g_wxhi);
    cudaGetSymbolAddress((void**)&wxlo, g_wxlo);
    cudaGetSymbolAddress((void**)&hhi,  g_hhi);
    cudaGetSymbolAddress((void**)&hlo,  g_hlo);
    cudaGetSymbolAddress((void**)&w1hi, g_w1hi);
    cudaGetSymbolAddress((void**)&w1lo, g_w1lo);
    cudaGetSymbolAddress((void**)&fc1p, g_fc1p);
    cudaGetSymbolAddress((void**)&fc1,  g_fc1);
    cudaGetSymbolAddress((void**)&fc2,  g_fc2);

    cudaFuncSetAttribute(gx_mma,  cudaFuncAttributeMaxDynamicSharedMemorySize, GX_SMEM);
    cudaFuncSetAttribute(fc1_mma, cudaFuncAttributeMaxDynamicSharedMemorySize, FC1_SMEM);

    // 1) x -> bf16 hi/lo
    cvt_split<<<16384, 256>>>(x, xhi, xlo);
    // 2) W_x2h -> bf16 hi/lo
    cvt_split<<<24, 256>>>(W_x2h, wxhi, wxlo);
    // 3) gx = x @ Wx^T (pipelined all-bf16)
    gx_mma<<<1024, 384, GX_SMEM>>>(xhi, xlo, wxhi, wxlo, gx);
    // 4) GRU scan v3 (profiled slot)
    gru_scan<<<128, 256>>>(gx, W_h2h, hhi, hlo);
    // 5) W1 -> bf16 hi/lo
    cvt_split<<<16384, 256>>>(W1, w1hi, w1lo);
    // 6) fc1 partials (3-stage cp.async pipeline) + 7) reduce
    fc1_mma<<<dim3(4, 2, SPLITK), 256, FC1_SMEM>>>(hhi, hlo, w1hi, w1lo, fc1p);
    reduce_fc1<<<128, 256>>>(fc1p, fc1);
    // 8) fc2 = relu(fc1) @ W2^T
    {
        dim3 grid(256 / 64, B_ / 64);
        gemm2<64, 64, 4, 4, true><<<grid, 256>>>(fc1, W2, fc2, B_, 256, 512);
    }
    // 9) logits + softmax
    fc3_softmax<<<B_, 128>>>(fc2, W3, out);
}

// round 15
// speedup vs baseline: 1.1256x; 1.0193x over previous
#include <cuda_runtime.h>
#include <cuda_bf16.h>
#include <math.h>
#include <stdint.h>

#define B_    256
#define S_    512
#define F_    128
#define H_    64
#define G_    192
#define C_    100
#define KTOT  32768
#define SPLITK 32
#define KCHUNK 1024      // KTOT/SPLITK
#define NKB   (KCHUNK / 64)

// ---------------- scratch (device globals; no allocation allowed) ----------
__device__ float          g_gx[131072 * 192];
__device__ __nv_bfloat16  g_xhi[131072 * 128];
__device__ __nv_bfloat16  g_xlo[131072 * 128];
__device__ __nv_bfloat16  g_wxhi[192 * 128];
__device__ __nv_bfloat16  g_wxlo[192 * 128];
__device__ __nv_bfloat16  g_hhi[256 * 32768];
__device__ __nv_bfloat16  g_hlo[256 * 32768];
__device__ __nv_bfloat16  g_w1hi[512 * 32768];
__device__ __nv_bfloat16  g_w1lo[512 * 32768];
__device__ float          g_fc1p[SPLITK * 256 * 512];
__device__ float          g_fc1[256 * 512];
__device__ float          g_fc2[256 * 256];

// ---------------- helpers ----------------------------------------------------
__device__ __forceinline__ uint32_t smem_u32(const void* p) {
    uint32_t a;
    asm("{ .reg .u64 t; cvta.to.shared.u64 t, %1; cvt.u32.u64 %0, t; }" : "=r"(a) : "l"(p));
    return a;
}
__device__ __forceinline__ void ldm4(uint32_t* r, uint32_t addr) {
    asm volatile("ldmatrix.sync.aligned.m8n8.x4.shared.b16 {%0,%1,%2,%3}, [%4];"
        : "=r"(r[0]), "=r"(r[1]), "=r"(r[2]), "=r"(r[3]) : "r"(addr));
}
#define MMA(c, a, b0, b1) \
    asm volatile("mma.sync.aligned.m16n8k16.row.col.f32.bf16.bf16.f32 " \
        "{%0,%1,%2,%3}, {%4,%5,%6,%7}, {%8,%9}, {%0,%1,%2,%3};" \
        : "+f"((c)[0]), "+f"((c)[1]), "+f"((c)[2]), "+f"((c)[3]) \
        : "r"((a)[0]), "r"((a)[1]), "r"((a)[2]), "r"((a)[3]), "r"(b0), "r"(b1))

#define CP16(dst, src) asm volatile("cp.async.cg.shared.global [%0], [%1], 16;" :: "r"(dst), "l"(src))
#define CPCOMMIT()     asm volatile("cp.async.commit_group;" ::: "memory")
#define CPWAIT(n)      asm volatile("cp.async.wait_group %0;" :: "n"(n) : "memory")

typedef unsigned long long u64;
__device__ __forceinline__ u64 pack2f(float lo, float hi) {
    u64 r; asm("mov.b64 %0, {%1, %2};" : "=l"(r) : "f"(lo), "f"(hi)); return r;
}
__device__ __forceinline__ u64 ffma2(u64 a, u64 b, u64 c) {
    u64 d; asm("fma.rn.f32x2 %0, %1, %2, %3;" : "=l"(d) : "l"(a), "l"(b), "l"(c)); return d;
}
__device__ __forceinline__ u64 fadd2(u64 a, u64 b) {
    u64 d; asm("add.rn.f32x2 %0, %1, %2;" : "=l"(d) : "l"(a), "l"(b)); return d;
}
__device__ __forceinline__ float2 unpack2(u64 v) {
    float2 f; asm("mov.b64 {%0, %1}, %2;" : "=f"(f.x), "=f"(f.y) : "l"(v)); return f;
}

__device__ __forceinline__ uint32_t packbf2(float a, float b) {
    __nv_bfloat162 t = __floats2bfloat162_rn(a, b);
    return *reinterpret_cast<uint32_t*>(&t);
}
__device__ __forceinline__ void split2(float a, float b, uint32_t& hi, uint32_t& lo) {
    __nv_bfloat16 ha = __float2bfloat16(a), hb = __float2bfloat16(b);
    __nv_bfloat162 h; h.x = ha; h.y = hb;
    hi = *reinterpret_cast<uint32_t*>(&h);
    lo = packbf2(a - __bfloat162float(ha), b - __bfloat162float(hb));
}

#define SA 72
#define ROWB 144

// ========== generic fp32 -> bf16 hi/lo streaming convert ====================
__global__ __launch_bounds__(256) void cvt_split(
    const float* __restrict__ src, __nv_bfloat16* __restrict__ hi, __nv_bfloat16* __restrict__ lo)
{
    size_t i = (size_t)blockIdx.x * 256 + threadIdx.x;
    float4 v = ((const float4*)src)[i];
    uint32_t h01, l01, h23, l23;
    split2(v.x, v.y, h01, l01);
    split2(v.z, v.w, h23, l23);
    *(uint2*)(hi + 4 * i) = make_uint2(h01, h23);
    *(uint2*)(lo + 4 * i) = make_uint2(l01, l23);
}

// ===== gx = x @ Wx^T (all-bf16 cp.async double-buffered, K=128) =============
#define GXP_AHI 0
#define GXP_ALO 18432
#define GXP_BHI 36864
#define GXP_BLO 64512
#define GXP_STG 92160
#define GX_SMEM (2 * GXP_STG)

__global__ __launch_bounds__(384, 1) void gx_mma(
    const __nv_bfloat16* __restrict__ Ahi_g, const __nv_bfloat16* __restrict__ Alo_g,
    const __nv_bfloat16* __restrict__ Bhi_g, const __nv_bfloat16* __restrict__ Blo_g,
    float* __restrict__ gx)
{
    extern __shared__ __align__(16) char sm[];
    const uint32_t sb = smem_u32(sm);
    const int tid = threadIdx.x;
    const int lane = tid & 31, wid = tid >> 5;
    const int wm = wid & 3, wn = wid >> 2;
    const int row0 = blockIdx.x * 128;

    float acc[2][8][4] = {};

    const uint32_t a_frag = (uint32_t)(wm * 32 + (lane & 15)) * ROWB + ((lane >> 4) * 16);
    const uint32_t b_frag = (uint32_t)(wn * 64 + ((lane >> 4) << 3) + (lane & 7)) * ROWB
                            + ((lane & 8) ? 16 : 0);

    auto load_stage = [&](int stg, int kbase) {
        const uint32_t base = sb + (uint32_t)stg * GXP_STG;
        for (int idx = tid; idx < 1024; idx += 384) {
            int r = idx >> 3, c8 = idx & 7;
            size_t go = (size_t)(row0 + r) * F_ + kbase + c8 * 8;
            uint32_t d = base + (uint32_t)(r * ROWB + c8 * 16);
            CP16(d + GXP_AHI, Ahi_g + go);
            CP16(d + GXP_ALO, Alo_g + go);
        }
        #pragma unroll
        for (int i = 0; i < 4; i++) {
            int idx = i * 384 + tid;
            int r = idx >> 3, c8 = idx & 7;
            size_t go = (size_t)r * F_ + kbase + c8 * 8;
            uint32_t d = base + (uint32_t)(r * ROWB + c8 * 16);
            CP16(d + GXP_BHI, Bhi_g + go);
            CP16(d + GXP_BLO, Blo_g + go);
        }
        CPCOMMIT();
    };

    load_stage(0, 0);
    load_stage(1, 64);

    for (int kb = 0; kb < 2; kb++) {
        if (kb == 0) { CPWAIT(1); } else { CPWAIT(0); }
        __syncthreads();

        const uint32_t stg = sb + (uint32_t)kb * GXP_STG;
        const uint32_t a_base = stg + GXP_AHI + a_frag;
        const uint32_t b_base = stg + GXP_BHI + b_frag;

        #pragma unroll
        for (int kk = 0; kk < 64; kk += 16) {
            uint32_t ah[2][4], al[2][4];
            ldm4(ah[0], a_base + kk * 2);
            ldm4(ah[1], a_base + 2304 + kk * 2);
            ldm4(al[0], a_base + (GXP_ALO - GXP_AHI) + kk * 2);
            ldm4(al[1], a_base + (GXP_ALO - GXP_AHI) + 2304 + kk * 2);
            #pragma unroll
            for (int nt = 0; nt < 4; nt++) {
                uint32_t bh[4], bl[4];
                ldm4(bh, b_base + nt * 2304 + kk * 2);
                ldm4(bl, b_base + (GXP_BLO - GXP_BHI) + nt * 2304 + kk * 2);
                #pragma unroll
                for (int mt = 0; mt < 2; mt++) {
                    MMA(acc[mt][nt * 2 + 0], ah[mt], bh[0], bh[1]);
                    MMA(acc[mt][nt * 2 + 1], ah[mt], bh[2], bh[3]);
                    MMA(acc[mt][nt * 2 + 0], ah[mt], bl[0], bl[1]);
                    MMA(acc[mt][nt * 2 + 1], ah[mt], bl[2], bl[3]);
                    MMA(acc[mt][nt * 2 + 0], al[mt], bh[0], bh[1]);
                    MMA(acc[mt][nt * 2 + 1], al[mt], bh[2], bh[3]);
                }
            }
        }
    }

    const int g = lane >> 2, tq = lane & 3;
    #pragma unroll
    for (int mt = 0; mt < 2; mt++) {
        #pragma unroll
        for (int n8 = 0; n8 < 8; n8++) {
            int row = row0 + wm * 32 + mt * 16 + g;
            int col = wn * 64 + n8 * 8 + tq * 2;
            *(float2*)&gx[(size_t)row * G_ + col]       = make_float2(acc[mt][n8][0], acc[mt][n8][1]);
            *(float2*)&gx[(size_t)(row + 8) * G_ + col] = make_float2(acc[mt][n8][2], acc[mt][n8][3]);
        }
    }
}

// ===== fc1 = hout @ W1^T : BM=256 (W1 read ONCE), BN=128, split-K=32 ========
// 512 threads (16 warps: 8M x 2N), 2-stage cp.async ring, grid (4, 32).
#define F1_AHI 0
#define F1_ALO 36864
#define F1_BHI 73728
#define F1_BLO 92160
#define F1_STG 110592
#define FC1_SMEM (2 * F1_STG)

__global__ __launch_bounds__(512, 1) void fc1_mma(
    const __nv_bfloat16* __restrict__ Ahi_g, const __nv_bfloat16* __restrict__ Alo_g,
    const __nv_bfloat16* __restrict__ Bhi_g, const __nv_bfloat16* __restrict__ Blo_g,
    float* __restrict__ part)
{
    extern __shared__ __align__(16) char sm[];
    const uint32_t sb = smem_u32(sm);
    const int tid = threadIdx.x;
    const int lane = tid & 31, wid = tid >> 5;
    const int wm = wid & 7, wn = wid >> 3;          // 8M x 2N warps
    const int col0 = blockIdx.x * 128;
    const int z = blockIdx.y;
    const int k0 = z * KCHUNK;

    float acc[2][8][4] = {};

    const uint32_t a_frag = (uint32_t)(wm * 32 + (lane & 15)) * ROWB + ((lane >> 4) * 16);
    const uint32_t b_frag = (uint32_t)(wn * 64 + ((lane >> 4) << 3) + (lane & 7)) * ROWB
                            + ((lane & 8) ? 16 : 0);

    auto load_stage = [&](int stg, int kbase) {
        const uint32_t base = sb + (uint32_t)stg * F1_STG;
        // A: 256 rows x 8 c8 = 2048 / 512 thr = 4 iters
        #pragma unroll
        for (int i = 0; i < 4; i++) {
            int idx = i * 512 + tid;
            int r = idx >> 3, c8 = idx & 7;
            size_t go = (size_t)r * KTOT + kbase + c8 * 8;
            uint32_t d = base + (uint32_t)(r * ROWB + c8 * 16);
            CP16(d + F1_AHI, Ahi_g + go);
            CP16(d + F1_ALO, Alo_g + go);
        }
        // B: 128 rows x 8 c8 = 1024 / 512 thr = 2 iters
        #pragma unroll
        for (int i = 0; i < 2; i++) {
            int idx = i * 512 + tid;
            int r = idx >> 3, c8 = idx & 7;
            size_t go = (size_t)(col0 + r) * KTOT + kbase + c8 * 8;
            uint32_t d = base + (uint32_t)(r * ROWB + c8 * 16);
            CP16(d + F1_BHI, Bhi_g + go);
            CP16(d + F1_BLO, Blo_g + go);
        }
        CPCOMMIT();
    };

    load_stage(0, k0);

    for (int kb = 0; kb < NKB; kb++) {
        if (kb + 1 < NKB) load_stage((kb + 1) & 1, k0 + (kb + 1) * 64);
        if (kb + 1 < NKB) { CPWAIT(1); } else { CPWAIT(0); }
        __syncthreads();

        const uint32_t stg = sb + (uint32_t)(kb & 1) * F1_STG;
        const uint32_t a_base = stg + F1_AHI + a_frag;
        const uint32_t b_base = stg + F1_BHI + b_frag;

        #pragma unroll
        for (int kk = 0; kk < 64; kk += 16) {
            uint32_t ah[2][4], al[2][4];
            ldm4(ah[0], a_base + kk * 2);
            ldm4(ah[1], a_base + 2304 + kk * 2);
            ldm4(al[0], a_base + (F1_ALO - F1_AHI) + kk * 2);
            ldm4(al[1], a_base + (F1_ALO - F1_AHI) + 2304 + kk * 2);
            #pragma unroll
            for (int nt = 0; nt < 4; nt++) {
                uint32_t bh[4], bl[4];
                ldm4(bh, b_base + nt * 2304 + kk * 2);
                ldm4(bl, b_base + (F1_BLO - F1_BHI) + nt * 2304 + kk * 2);
                #pragma unroll
                for (int mt = 0; mt < 2; mt++) {
                    MMA(acc[mt][nt * 2 + 0], ah[mt], bh[0], bh[1]);
                    MMA(acc[mt][nt * 2 + 1], ah[mt], bh[2], bh[3]);
                    MMA(acc[mt][nt * 2 + 0], ah[mt], bl[0], bl[1]);
                    MMA(acc[mt][nt * 2 + 1], ah[mt], bl[2], bl[3]);
                    MMA(acc[mt][nt * 2 + 0], al[mt], bh[0], bh[1]);
                    MMA(acc[mt][nt * 2 + 1], al[mt], bh[2], bh[3]);
                }
            }
        }
        __syncthreads();
    }

    const int g = lane >> 2, tq = lane & 3;
    const size_t obase = (size_t)z * 256 * 512;
    #pragma unroll
    for (int mt = 0; mt < 2; mt++) {
        #pragma unroll
        for (int n8 = 0; n8 < 8; n8++) {
            int row = wm * 32 + mt * 16 + g;
            int col = col0 + wn * 64 + n8 * 8 + tq * 2;
            *(float2*)&part[obase + (size_t)row * 512 + col]       = make_float2(acc[mt][n8][0], acc[mt][n8][1]);
            *(float2*)&part[obase + (size_t)(row + 8) * 512 + col] = make_float2(acc[mt][n8][2], acc[mt][n8][3]);
        }
    }
}

// ---------------- split-K reduce (32 slabs) ---------------------------------
__global__ __launch_bounds__(256) void reduce_fc1(
    const float* __restrict__ p, float* __restrict__ o)
{
    int i = blockIdx.x * 256 + threadIdx.x;
    const float4* p4 = (const float4*)p;
    float4 s = make_float4(0.f, 0.f, 0.f, 0.f);
    #pragma unroll
    for (int sk = 0; sk < SPLITK; sk++) {
        float4 v = p4[(size_t)sk * 32768 + i];
        s.x += v.x; s.y += v.y; s.z += v.z; s.w += v.w;
    }
    ((float4*)o)[i] = s;
}

// ---------------- fp32 gemm (fc2 only) -------------------------------------
template <int BM, int BN, int TM, int TN, bool RELU_A>
__global__ __launch_bounds__(256) void gemm2(
    const float* __restrict__ A, const float* __restrict__ Bm, float* __restrict__ C,
    int M, int N, int K)
{
    __shared__ float As[16][BM];
    __shared__ float Bs[16][BN];
    const int row0 = blockIdx.y * BM;
    const int col0 = blockIdx.x * BN;
    const int tid = threadIdx.x;
    const int tx = tid & 15, ty = tid >> 4;
    const int lrow = tid >> 2, lk = (tid & 3) * 4;

    float acc[TM][TN] = {};
    for (int k = 0; k < K; k += 16) {
        #pragma unroll
        for (int j = 0; j < BM / 64; j++) {
            int r = j * 64 + lrow;
            float4 v = *(const float4*)&A[(size_t)(row0 + r) * K + k + lk];
            if (RELU_A) {
                v.x = fmaxf(v.x, 0.f); v.y = fmaxf(v.y, 0.f);
                v.z = fmaxf(v.z, 0.f); v.w = fmaxf(v.w, 0.f);
            }
            As[lk + 0][r] = v.x; As[lk + 1][r] = v.y;
            As[lk + 2][r] = v.z; As[lk + 3][r] = v.w;
        }
        #pragma unroll
        for (int j = 0; j < BN / 64; j++) {
            int r = j * 64 + lrow;
            float4 v = *(const float4*)&Bm[(size_t)(col0 + r) * K + k + lk];
            Bs[lk + 0][r] = v.x; Bs[lk + 1][r] = v.y;
            Bs[lk + 2][r] = v.z; Bs[lk + 3][r] = v.w;
        }
        __syncthreads();
        #pragma unroll
        for (int kk = 0; kk < 16; kk++) {
            float a[TM], b[TN];
            #pragma unroll
            for (int i = 0; i < TM; i++) a[i] = As[kk][ty * TM + i];
            #pragma unroll
            for (int j = 0; j < TN; j++) b[j] = Bs[kk][tx * TN + j];
            #pragma unroll
            for (int i = 0; i < TM; i++)
                #pragma unroll
                for (int j = 0; j < TN; j++) acc[i][j] += a[i] * b[j];
        }
        __syncthreads();
    }
    #pragma unroll
    for (int i = 0; i < TM; i++)
        #pragma unroll
        for (int j = 0; j < TN; j++)
            C[(size_t)(row0 + ty * TM + i) * N + col0 + tx * TN + j] = acc[i][j];
}

// ========== GRU v3 (R8/R11-best: 2 thr/unit, shfl, 1 named bar/step) ========
__device__ __forceinline__ float fast_sigmoid(float x) {
    return __fdividef(1.0f, 1.0f + __expf(-x));
}
__device__ __forceinline__ float fast_tanh(float x) {
    return 1.0f - __fdividef(2.0f, __expf(2.0f * x) + 1.0f);
}
#define BARG(id) asm volatile("bar.sync %0, 128;" :: "r"(id) : "memory")

__global__ __launch_bounds__(256) void gru_scan(
    const float* __restrict__ gx, const float* __restrict__ W_h2h,
    __nv_bfloat16* __restrict__ hhi, __nv_bfloat16* __restrict__ hlo)
{
    const int g = threadIdx.x >> 7;
    const int t = threadIdx.x & 127;
    const int u = t >> 1;
    const int half = t & 1;
    const int b = blockIdx.x * 2 + g;
    const int barid = 1 + g;

    __shared__ __align__(16) float sh[2][2][H_];

    u64 w2r[16], w2z[16], w2n[16];
    {
        const float* wr = W_h2h + (size_t)u * H_ + half * 32;
        const float* wz = W_h2h + (size_t)(64 + u) * H_ + half * 32;
        const float* wn = W_h2h + (size_t)(128 + u) * H_ + half * 32;
        #pragma unroll
        for (int j = 0; j < 16; j++) {
            float2 a = *(const float2*)(wr + 2 * j); w2r[j] = pack2f(a.x, a.y);
            float2 bz = *(const float2*)(wz + 2 * j); w2z[j] = pack2f(bz.x, bz.y);
            float2 cn = *(const float2*)(wn + 2 * j); w2n[j] = pack2f(cn.x, cn.y);
        }
    }

    if (half == 0) sh[0][g][u] = 0.f;
    __syncthreads();

    const size_t base = (size_t)b * S_ * G_;
    float pir[4], pii[4], pin[4];
    if (half == 0) {
        #pragma unroll
        for (int d = 0; d < 4; d++) {
            size_t o = base + (size_t)d * G_;
            pir[d] = gx[o + u];
            pii[d] = gx[o + 64 + u];
            pin[d] = gx[o + 128 + u];
        }
    }

    float hprev = 0.f;

    for (int s4 = 0; s4 < S_; s4 += 4) {
        #pragma unroll
        for (int ph = 0; ph < 4; ph++) {
            const int s = s4 + ph;
            const int cur = ph & 1;
            const int nxt = cur ^ 1;

            const u64* hp = (const u64*)&sh[cur][g][half * 32];
            u64 ar0 = 0ull, ar1 = 0ull, az0 = 0ull, az1 = 0ull, an0 = 0ull, an1 = 0ull;
            #pragma unroll
            for (int j = 0; j < 16; j += 2) {
                u64 h0 = hp[j], h1 = hp[j + 1];
                ar0 = ffma2(w2r[j], h0, ar0); ar1 = ffma2(w2r[j + 1], h1, ar1);
                az0 = ffma2(w2z[j], h0, az0); az1 = ffma2(w2z[j + 1], h1, az1);
                an0 = ffma2(w2n[j], h0, an0); an1 = ffma2(w2n[j + 1], h1, an1);
            }
            float2 fr = unpack2(fadd2(ar0, ar1));
            float2 fz = unpack2(fadd2(az0, az1));
            float2 fn = unpack2(fadd2(an0, an1));
            float rdot = fr.x + fr.y;
            float zdot = fz.x + fz.y;
            float ndot = fn.x + fn.y;
            rdot += __shfl_xor_sync(0xffffffffu, rdot, 1);
            zdot += __shfl_xor_sync(0xffffffffu, zdot, 1);
            ndot += __shfl_xor_sync(0xffffffffu, ndot, 1);

            if (half == 0) {
                float r = fast_sigmoid(pir[ph] + rdot);
                float z = fast_sigmoid(pii[ph] + zdot);
                float n = fast_tanh(pin[ph] + r * ndot);
                float hn = n + z * (hprev - n);
                hprev = hn;
                sh[nxt][g][u] = hn;
                size_t idx = ((size_t)b * S_ + s) * H_ + u;
                __nv_bfloat16 hb = __float2bfloat16(hn);
                hhi[idx] = hb;
                hlo[idx] = __float2bfloat16(hn - __bfloat162float(hb));
                if (s + 4 < S_) {
                    size_t nb = base + (size_t)(s + 4) * G_;
                    pir[ph] = gx[nb + u];
                    pii[ph] = gx[nb + 64 + u];
                    pin[ph] = gx[nb + 128 + u];
                }
            }
            BARG(barid);
        }
    }
}

// ---------------- fc3 + softmax --------------------------------------------
__global__ __launch_bounds__(128) void fc3_softmax(
    const float* __restrict__ fc2, const float* __restrict__ W3,
    float* __restrict__ out)
{
    const int b = blockIdx.x;
    const int t = threadIdx.x;
    __shared__ float sa[256];
    __shared__ float slog[C_];
    __shared__ float red[128];

    for (int k = t; k < 256; k += 128) sa[k] = fmaxf(fc2[b * 256 + k], 0.f);
    __syncthreads();

    float acc = 0.f;
    if (t < C_) {
        const float* wr = &W3[t * 256];
        #pragma unroll 8
        for (int k = 0; k < 256; k++) acc += sa[k] * wr[k];
        slog[t] = acc;
    }
    __syncthreads();

    float m = -1e30f;
    for (int k = t; k < C_; k += 128) m = fmaxf(m, slog[k]);
    red[t] = m; __syncthreads();
    for (int st = 64; st > 0; st >>= 1) {
        if (t < st) red[t] = fmaxf(red[t], red[t + st]);
        __syncthreads();
    }
    float mx = red[0];
    __syncthreads();

    float e = 0.f;
    if (t < C_) { e = __expf(slog[t] - mx); slog[t] = e; }
    red[t] = (t < C_) ? e : 0.f; __syncthreads();
    for (int st = 64; st > 0; st >>= 1) {
        if (t < st) red[t] += red[t + st];
        __syncthreads();
    }
    float inv = 1.0f / red[0];
    __syncthreads();

    if (t < C_) out[b * C_ + t] = slog[t] * inv;
}

// ---------------- launch ----------------------------------------------------
extern "C" void kernel_launch(void* const* d_in, const int* in_sizes, int n_in,
                              void* d_out, int out_size)
{
    const float* x     = (const float*)d_in[0];
    const float* W_x2h = (const float*)d_in[1];
    const float* W_h2h = (const float*)d_in[2];
    const float* W1    = (const float*)d_in[3];
    const float* W2    = (const float*)d_in[4];
    const float* W3    = (const float*)d_in[5];
    float* out = (float*)d_out;

    float *gx, *fc1p, *fc1, *fc2;
    __nv_bfloat16 *xhi, *xlo, *wxhi, *wxlo, *hhi, *hlo, *w1hi, *w1lo;
    cudaGetSymbolAddress((void**)&gx,   g_gx);
    cudaGetSymbolAddress((void**)&xhi,  g_xhi);
    cudaGetSymbolAddress((void**)&xlo,  g_xlo);
    cudaGetSymbolAddress((void**)&wxhi, g_wxhi);
    cudaGetSymbolAddress((void**)&wxlo, g_wxlo);
    cudaGetSymbolAddress((void**)&hhi,  g_hhi);
    cudaGetSymbolAddress((void**)&hlo,  g_hlo);
    cudaGetSymbolAddress((void**)&w1hi, g_w1hi);
    cudaGetSymbolAddress((void**)&w1lo, g_w1lo);
    cudaGetSymbolAddress((void**)&fc1p, g_fc1p);
    cudaGetSymbolAddress((void**)&fc1,  g_fc1);
    cudaGetSymbolAddress((void**)&fc2,  g_fc2);

    cudaFuncSetAttribute(gx_mma,  cudaFuncAttributeMaxDynamicSharedMemorySize, GX_SMEM);
    cudaFuncSetAttribute(fc1_mma, cudaFuncAttributeMaxDynamicSharedMemorySize, FC1_SMEM);

    // 1) x -> bf16 hi/lo
    cvt_split<<<16384, 256>>>(x, xhi, xlo);
    // 2) W_x2h -> bf16 hi/lo
    cvt_split<<<24, 256>>>(W_x2h, wxhi, wxlo);
    // 3) gx = x @ Wx^T (pipelined all-bf16)
    gx_mma<<<1024, 384, GX_SMEM>>>(xhi, xlo, wxhi, wxlo, gx);
    // 4) GRU scan v3 (profiled slot)
    gru_scan<<<128, 256>>>(gx, W_h2h, hhi, hlo);
    // 5) W1 -> bf16 hi/lo
    cvt_split<<<16384, 256>>>(W1, w1hi, w1lo);
    // 6) fc1 partials (BM=256: W1 read once) + 7) reduce
    fc1_mma<<<dim3(4, SPLITK), 512, FC1_SMEM>>>(hhi, hlo, w1hi, w1lo, fc1p);
    reduce_fc1<<<128, 256>>>(fc1p, fc1);
    // 8) fc2 = relu(fc1) @ W2^T
    {
        dim3 grid(256 / 64, B_ / 64);
        gemm2<64, 64, 4, 4, true><<<grid, 256>>>(fc1, W2, fc2, B_, 256, 512);
    }
    // 9) logits + softmax
    fc3_softmax<<<B_, 128>>>(fc2, W3, out);
}

// round 16
// speedup vs baseline: 1.1608x; 1.0313x over previous
#include <cuda_runtime.h>
#include <cuda_bf16.h>
#include <math.h>
#include <stdint.h>

#define B_    256
#define S_    512
#define F_    128
#define H_    64
#define G_    192
#define C_    100
#define KTOT  32768
#define SPLITK 32
#define KCHUNK 1024      // KTOT/SPLITK
#define NKB   (KCHUNK / 64)

// ---------------- scratch (device globals; no allocation allowed) ----------
__device__ float          g_gx[131072 * 192];
__device__ __nv_bfloat16  g_wxhi[192 * 128];
__device__ __nv_bfloat16  g_wxlo[192 * 128];
__device__ __nv_bfloat16  g_hhi[256 * 32768];
__device__ __nv_bfloat16  g_hlo[256 * 32768];
__device__ __nv_bfloat16  g_w1hi[512 * 32768];
__device__ __nv_bfloat16  g_w1lo[512 * 32768];
__device__ float          g_fc1p[SPLITK * 256 * 512];
__device__ float          g_fc1[256 * 512];
__device__ float          g_fc2[256 * 256];

// ---------------- helpers ----------------------------------------------------
__device__ __forceinline__ uint32_t smem_u32(const void* p) {
    uint32_t a;
    asm("{ .reg .u64 t; cvta.to.shared.u64 t, %1; cvt.u32.u64 %0, t; }" : "=r"(a) : "l"(p));
    return a;
}
__device__ __forceinline__ void ldm4(uint32_t* r, uint32_t addr) {
    asm volatile("ldmatrix.sync.aligned.m8n8.x4.shared.b16 {%0,%1,%2,%3}, [%4];"
        : "=r"(r[0]), "=r"(r[1]), "=r"(r[2]), "=r"(r[3]) : "r"(addr));
}
#define MMA(c, a, b0, b1) \
    asm volatile("mma.sync.aligned.m16n8k16.row.col.f32.bf16.bf16.f32 " \
        "{%0,%1,%2,%3}, {%4,%5,%6,%7}, {%8,%9}, {%0,%1,%2,%3};" \
        : "+f"((c)[0]), "+f"((c)[1]), "+f"((c)[2]), "+f"((c)[3]) \
        : "r"((a)[0]), "r"((a)[1]), "r"((a)[2]), "r"((a)[3]), "r"(b0), "r"(b1))

#define CP16(dst, src) asm volatile("cp.async.cg.shared.global [%0], [%1], 16;" :: "r"(dst), "l"(src))
#define CPCOMMIT()     asm volatile("cp.async.commit_group;" ::: "memory")
#define CPWAIT(n)      asm volatile("cp.async.wait_group %0;" :: "n"(n) : "memory")

typedef unsigned long long u64;
__device__ __forceinline__ u64 pack2f(float lo, float hi) {
    u64 r; asm("mov.b64 %0, {%1, %2};" : "=l"(r) : "f"(lo), "f"(hi)); return r;
}
__device__ __forceinline__ u64 ffma2(u64 a, u64 b, u64 c) {
    u64 d; asm("fma.rn.f32x2 %0, %1, %2, %3;" : "=l"(d) : "l"(a), "l"(b), "l"(c)); return d;
}
__device__ __forceinline__ u64 fadd2(u64 a, u64 b) {
    u64 d; asm("add.rn.f32x2 %0, %1, %2;" : "=l"(d) : "l"(a), "l"(b)); return d;
}
__device__ __forceinline__ float2 unpack2(u64 v) {
    float2 f; asm("mov.b64 {%0, %1}, %2;" : "=f"(f.x), "=f"(f.y) : "l"(v)); return f;
}

__device__ __forceinline__ uint32_t packbf2(float a, float b) {
    __nv_bfloat162 t = __floats2bfloat162_rn(a, b);
    return *reinterpret_cast<uint32_t*>(&t);
}
__device__ __forceinline__ void split2(float a, float b, uint32_t& hi, uint32_t& lo) {
    __nv_bfloat16 ha = __float2bfloat16(a), hb = __float2bfloat16(b);
    __nv_bfloat162 h; h.x = ha; h.y = hb;
    hi = *reinterpret_cast<uint32_t*>(&h);
    lo = packbf2(a - __bfloat162float(ha), b - __bfloat162float(hb));
}

#define SA 72
#define ROWB 144

// ========== generic fp32 -> bf16 hi/lo streaming convert (Wx only) ==========
__global__ __launch_bounds__(256) void cvt_split(
    const float* __restrict__ src, __nv_bfloat16* __restrict__ hi, __nv_bfloat16* __restrict__ lo)
{
    size_t i = (size_t)blockIdx.x * 256 + threadIdx.x;
    float4 v = ((const float4*)src)[i];
    uint32_t h01, l01, h23, l23;
    split2(v.x, v.y, h01, l01);
    split2(v.z, v.w, h23, l23);
    *(uint2*)(hi + 4 * i) = make_uint2(h01, h23);
    *(uint2*)(lo + 4 * i) = make_uint2(l01, l23);
}

// ===== gx = x @ Wx^T : A fp32 converted in-kernel, B pre-split resident =====
// 1024 blocks x 384 threads (12 warps: 4M x 3N), tile 128x192, K=128 (2 halves)
#define GB_HI0 0
#define GB_LO0 27648
#define GB_HI1 55296
#define GB_LO1 82944
#define GA_HI  110592
#define GA_LO  129024
#define GX_SMEM 147456

__global__ __launch_bounds__(384, 1) void gx_mma(
    const float* __restrict__ x,
    const __nv_bfloat16* __restrict__ Bhi_g, const __nv_bfloat16* __restrict__ Blo_g,
    float* __restrict__ gx)
{
    extern __shared__ __align__(16) char sm[];
    const uint32_t sb = smem_u32(sm);
    const int tid = threadIdx.x;
    const int lane = tid & 31, wid = tid >> 5;
    const int wm = wid & 3, wn = wid >> 2;
    const int row0 = blockIdx.x * 128;

    __nv_bfloat16* AHI = (__nv_bfloat16*)(sm + GA_HI);
    __nv_bfloat16* ALO = (__nv_bfloat16*)(sm + GA_LO);

    float acc[2][8][4] = {};

    const uint32_t a_frag = (uint32_t)(wm * 32 + (lane & 15)) * ROWB + ((lane >> 4) * 16);
    const uint32_t b_frag = (uint32_t)(wn * 64 + ((lane >> 4) << 3) + (lane & 7)) * ROWB
                            + ((lane & 8) ? 16 : 0);

    // B: whole 192x128 (both K halves), hi+lo, via cp.async. 3072 combos / 384 = 8.
    #pragma unroll
    for (int it = 0; it < 8; it++) {
        int idx = it * 384 + tid;
        int kh = (idx >= 1536) ? 1 : 0;
        int rem = idx - kh * 1536;
        int r = rem >> 3, c8 = rem & 7;
        uint32_t dhi = sb + (kh ? GB_HI1 : GB_HI0) + (uint32_t)(r * ROWB + c8 * 16);
        size_t go = (size_t)r * F_ + kh * 64 + c8 * 8;
        CP16(dhi, Bhi_g + go);
        CP16(dhi + (GB_LO0 - GB_HI0), Blo_g + go);
    }
    CPCOMMIT();

    // A half loader: raw fp32 LDG -> split -> STS (2048 float4 / 384 thr)
    auto loadA = [&](int kh) {
        #pragma unroll
        for (int it = 0; it < 6; it++) {
            int idx = it * 384 + tid;
            if (idx < 2048) {
                int r = idx >> 4, c4 = idx & 15;
                float4 v = *(const float4*)(x + (size_t)(row0 + r) * F_ + kh * 64 + c4 * 4);
                uint32_t h01, l01, h23, l23;
                split2(v.x, v.y, h01, l01); split2(v.z, v.w, h23, l23);
                int o = r * SA + c4 * 4;
                *(uint2*)(AHI + o) = make_uint2(h01, h23);
                *(uint2*)(ALO + o) = make_uint2(l01, l23);
            }
        }
    };

    loadA(0);
    CPWAIT(0);
    __syncthreads();

    #pragma unroll
    for (int kh = 0; kh < 2; kh++) {
        if (kh) {
            __syncthreads();   // everyone done with A half 0 fragments
            loadA(1);
            __syncthreads();
        }
        const uint32_t a_base = sb + GA_HI + a_frag;
        const uint32_t b_base = sb + (kh ? GB_HI1 : GB_HI0) + b_frag;

        #pragma unroll
        for (int kk = 0; kk < 64; kk += 16) {
            uint32_t ah[2][4], al[2][4];
            ldm4(ah[0], a_base + kk * 2);
            ldm4(ah[1], a_base + 2304 + kk * 2);
            ldm4(al[0], a_base + (GA_LO - GA_HI) + kk * 2);
            ldm4(al[1], a_base + (GA_LO - GA_HI) + 2304 + kk * 2);
            #pragma unroll
            for (int nt = 0; nt < 4; nt++) {
                uint32_t bh[4], bl[4];
                ldm4(bh, b_base + nt * 2304 + kk * 2);
                ldm4(bl, b_base + (GB_LO0 - GB_HI0) + nt * 2304 + kk * 2);
                #pragma unroll
                for (int mt = 0; mt < 2; mt++) {
                    MMA(acc[mt][nt * 2 + 0], ah[mt], bh[0], bh[1]);
                    MMA(acc[mt][nt * 2 + 1], ah[mt], bh[2], bh[3]);
                    MMA(acc[mt][nt * 2 + 0], ah[mt], bl[0], bl[1]);
                    MMA(acc[mt][nt * 2 + 1], ah[mt], bl[2], bl[3]);
                    MMA(acc[mt][nt * 2 + 0], al[mt], bh[0], bh[1]);
                    MMA(acc[mt][nt * 2 + 1], al[mt], bh[2], bh[3]);
                }
            }
        }
    }

    const int g = lane >> 2, tq = lane & 3;
    #pragma unroll
    for (int mt = 0; mt < 2; mt++) {
        #pragma unroll
        for (int n8 = 0; n8 < 8; n8++) {
            int row = row0 + wm * 32 + mt * 16 + g;
            int col = wn * 64 + n8 * 8 + tq * 2;
            *(float2*)&gx[(size_t)row * G_ + col]       = make_float2(acc[mt][n8][0], acc[mt][n8][1]);
            *(float2*)&gx[(size_t)(row + 8) * G_ + col] = make_float2(acc[mt][n8][2], acc[mt][n8][3]);
        }
    }
}

// ===== fc1 = hout @ W1^T : BM=256 (W1 read once), BN=128, split-K=32 ========
#define F1_AHI 0
#define F1_ALO 36864
#define F1_BHI 73728
#define F1_BLO 92160
#define F1_STG 110592
#define FC1_SMEM (2 * F1_STG)

__global__ __launch_bounds__(512, 1) void fc1_mma(
    const __nv_bfloat16* __restrict__ Ahi_g, const __nv_bfloat16* __restrict__ Alo_g,
    const __nv_bfloat16* __restrict__ Bhi_g, const __nv_bfloat16* __restrict__ Blo_g,
    float* __restrict__ part)
{
    extern __shared__ __align__(16) char sm[];
    const uint32_t sb = smem_u32(sm);
    const int tid = threadIdx.x;
    const int lane = tid & 31, wid = tid >> 5;
    const int wm = wid & 7, wn = wid >> 3;
    const int col0 = blockIdx.x * 128;
    const int z = blockIdx.y;
    const int k0 = z * KCHUNK;

    float acc[2][8][4] = {};

    const uint32_t a_frag = (uint32_t)(wm * 32 + (lane & 15)) * ROWB + ((lane >> 4) * 16);
    const uint32_t b_frag = (uint32_t)(wn * 64 + ((lane >> 4) << 3) + (lane & 7)) * ROWB
                            + ((lane & 8) ? 16 : 0);

    auto load_stage = [&](int stg, int kbase) {
        const uint32_t base = sb + (uint32_t)stg * F1_STG;
        #pragma unroll
        for (int i = 0; i < 4; i++) {
            int idx = i * 512 + tid;
            int r = idx >> 3, c8 = idx & 7;
            size_t go = (size_t)r * KTOT + kbase + c8 * 8;
            uint32_t d = base + (uint32_t)(r * ROWB + c8 * 16);
            CP16(d + F1_AHI, Ahi_g + go);
            CP16(d + F1_ALO, Alo_g + go);
        }
        #pragma unroll
        for (int i = 0; i < 2; i++) {
            int idx = i * 512 + tid;
            int r = idx >> 3, c8 = idx & 7;
            size_t go = (size_t)(col0 + r) * KTOT + kbase + c8 * 8;
            uint32_t d = base + (uint32_t)(r * ROWB + c8 * 16);
            CP16(d + F1_BHI, Bhi_g + go);
            CP16(d + F1_BLO, Blo_g + go);
        }
        CPCOMMIT();
    };

    load_stage(0, k0);

    for (int kb = 0; kb < NKB; kb++) {
        if (kb + 1 < NKB) load_stage((kb + 1) & 1, k0 + (kb + 1) * 64);
        if (kb + 1 < NKB) { CPWAIT(1); } else { CPWAIT(0); }
        __syncthreads();

        const uint32_t stg = sb + (uint32_t)(kb & 1) * F1_STG;
        const uint32_t a_base = stg + F1_AHI + a_frag;
        const uint32_t b_base = stg + F1_BHI + b_frag;

        #pragma unroll
        for (int kk = 0; kk < 64; kk += 16) {
            uint32_t ah[2][4], al[2][4];
            ldm4(ah[0], a_base + kk * 2);
            ldm4(ah[1], a_base + 2304 + kk * 2);
            ldm4(al[0], a_base + (F1_ALO - F1_AHI) + kk * 2);
            ldm4(al[1], a_base + (F1_ALO - F1_AHI) + 2304 + kk * 2);
            #pragma unroll
            for (int nt = 0; nt < 4; nt++) {
                uint32_t bh[4], bl[4];
                ldm4(bh, b_base + nt * 2304 + kk * 2);
                ldm4(bl, b_base + (F1_BLO - F1_BHI) + nt * 2304 + kk * 2);
                #pragma unroll
                for (int mt = 0; mt < 2; mt++) {
                    MMA(acc[mt][nt * 2 + 0], ah[mt], bh[0], bh[1]);
                    MMA(acc[mt][nt * 2 + 1], ah[mt], bh[2], bh[3]);
                    MMA(acc[mt][nt * 2 + 0], ah[mt], bl[0], bl[1]);
                    MMA(acc[mt][nt * 2 + 1], ah[mt], bl[2], bl[3]);
                    MMA(acc[mt][nt * 2 + 0], al[mt], bh[0], bh[1]);
                    MMA(acc[mt][nt * 2 + 1], al[mt], bh[2], bh[3]);
                }
            }
        }
        __syncthreads();
    }

    const int g = lane >> 2, tq = lane & 3;
    const size_t obase = (size_t)z * 256 * 512;
    #pragma unroll
    for (int mt = 0; mt < 2; mt++) {
        #pragma unroll
        for (int n8 = 0; n8 < 8; n8++) {
            int row = wm * 32 + mt * 16 + g;
            int col = col0 + wn * 64 + n8 * 8 + tq * 2;
            *(float2*)&part[obase + (size_t)row * 512 + col]       = make_float2(acc[mt][n8][0], acc[mt][n8][1]);
            *(float2*)&part[obase + (size_t)(row + 8) * 512 + col] = make_float2(acc[mt][n8][2], acc[mt][n8][3]);
        }
    }
}

// ---------------- split-K reduce --------------------------------------------
__global__ __launch_bounds__(256) void reduce_fc1(
    const float* __restrict__ p, float* __restrict__ o)
{
    int i = blockIdx.x * 256 + threadIdx.x;
    const float4* p4 = (const float4*)p;
    float4 s = make_float4(0.f, 0.f, 0.f, 0.f);
    #pragma unroll
    for (int sk = 0; sk < SPLITK; sk++) {
        float4 v = p4[(size_t)sk * 32768 + i];
        s.x += v.x; s.y += v.y; s.z += v.z; s.w += v.w;
    }
    ((float4*)o)[i] = s;
}

// ---------------- fp32 gemm (fc2 only) --------------------------------------
template <int BM, int BN, int TM, int TN, bool RELU_A>
__global__ __launch_bounds__(256) void gemm2(
    const float* __restrict__ A, const float* __restrict__ Bm, float* __restrict__ C,
    int M, int N, int K)
{
    __shared__ float As[16][BM];
    __shared__ float Bs[16][BN];
    const int row0 = blockIdx.y * BM;
    const int col0 = blockIdx.x * BN;
    const int tid = threadIdx.x;
    const int tx = tid & 15, ty = tid >> 4;
    const int lrow = tid >> 2, lk = (tid & 3) * 4;

    float acc[TM][TN] = {};
    for (int k = 0; k < K; k += 16) {
        #pragma unroll
        for (int j = 0; j < BM / 64; j++) {
            int r = j * 64 + lrow;
            float4 v = *(const float4*)&A[(size_t)(row0 + r) * K + k + lk];
            if (RELU_A) {
                v.x = fmaxf(v.x, 0.f); v.y = fmaxf(v.y, 0.f);
                v.z = fmaxf(v.z, 0.f); v.w = fmaxf(v.w, 0.f);
            }
            As[lk + 0][r] = v.x; As[lk + 1][r] = v.y;
            As[lk + 2][r] = v.z; As[lk + 3][r] = v.w;
        }
        #pragma unroll
        for (int j = 0; j < BN / 64; j++) {
            int r = j * 64 + lrow;
            float4 v = *(const float4*)&Bm[(size_t)(col0 + r) * K + k + lk];
            Bs[lk + 0][r] = v.x; Bs[lk + 1][r] = v.y;
            Bs[lk + 2][r] = v.z; Bs[lk + 3][r] = v.w;
        }
        __syncthreads();
        #pragma unroll
        for (int kk = 0; kk < 16; kk++) {
            float a[TM], b[TN];
            #pragma unroll
            for (int i = 0; i < TM; i++) a[i] = As[kk][ty * TM + i];
            #pragma unroll
            for (int j = 0; j < TN; j++) b[j] = Bs[kk][tx * TN + j];
            #pragma unroll
            for (int i = 0; i < TM; i++)
                #pragma unroll
                for (int j = 0; j < TN; j++) acc[i][j] += a[i] * b[j];
        }
        __syncthreads();
    }
    #pragma unroll
    for (int i = 0; i < TM; i++)
        #pragma unroll
        for (int j = 0; j < TN; j++)
            C[(size_t)(row0 + ty * TM + i) * N + col0 + tx * TN + j] = acc[i][j];
}

// ========== GRU v3 + fused W1 convert warp-group ============================
__device__ __forceinline__ float fast_sigmoid(float x) {
    return __fdividef(1.0f, 1.0f + __expf(-x));
}
__device__ __forceinline__ float fast_tanh(float x) {
    return 1.0f - __fdividef(2.0f, __expf(2.0f * x) + 1.0f);
}
#define BARG(id) asm volatile("bar.sync %0, 128;" :: "r"(id) : "memory")

// 128 blocks x 384 threads: threads 0-255 run the v3 GRU (2 chains, named
// bars), threads 256-383 stream-convert this block's 1/128 slice of W1.
__global__ __launch_bounds__(384) void gru_scan(
    const float* __restrict__ gx, const float* __restrict__ W_h2h,
    __nv_bfloat16* __restrict__ hhi, __nv_bfloat16* __restrict__ hlo,
    const float* __restrict__ W1,
    __nv_bfloat16* __restrict__ w1hi, __nv_bfloat16* __restrict__ w1lo)
{
    __shared__ __align__(16) float sh[2][2][H_];

    if (threadIdx.x >= 256) {
        // W1 convert warp-group: 128 threads x 256 float4 each
        if ((threadIdx.x & 127) == 0) { /* nothing */ }
        __syncthreads();                       // pair with GRU init sync
        const int ct = threadIdx.x - 256;
        const float4* src = (const float4*)W1;
        size_t base4 = (size_t)blockIdx.x * 32768 + ct;
        #pragma unroll 4
        for (int i = 0; i < 256; i++) {
            size_t idx = base4 + (size_t)i * 128;
            float4 v = src[idx];
            uint32_t h01, l01, h23, l23;
            split2(v.x, v.y, h01, l01);
            split2(v.z, v.w, h23, l23);
            *(uint2*)(w1hi + 4 * idx) = make_uint2(h01, h23);
            *(uint2*)(w1lo + 4 * idx) = make_uint2(l01, l23);
        }
        return;
    }

    const int g = threadIdx.x >> 7;
    const int t = threadIdx.x & 127;
    const int u = t >> 1;
    const int half = t & 1;
    const int b = blockIdx.x * 2 + g;
    const int barid = 1 + g;

    u64 w2r[16], w2z[16], w2n[16];
    {
        const float* wr = W_h2h + (size_t)u * H_ + half * 32;
        const float* wz = W_h2h + (size_t)(64 + u) * H_ + half * 32;
        const float* wn = W_h2h + (size_t)(128 + u) * H_ + half * 32;
        #pragma unroll
        for (int j = 0; j < 16; j++) {
            float2 a = *(const float2*)(wr + 2 * j); w2r[j] = pack2f(a.x, a.y);
            float2 bz = *(const float2*)(wz + 2 * j); w2z[j] = pack2f(bz.x, bz.y);
            float2 cn = *(const float2*)(wn + 2 * j); w2n[j] = pack2f(cn.x, cn.y);
        }
    }

    if (half == 0) sh[0][g][u] = 0.f;
    __syncthreads();

    const size_t base = (size_t)b * S_ * G_;
    float pir[4], pii[4], pin[4];
    if (half == 0) {
        #pragma unroll
        for (int d = 0; d < 4; d++) {
            size_t o = base + (size_t)d * G_;
            pir[d] = gx[o + u];
            pii[d] = gx[o + 64 + u];
            pin[d] = gx[o + 128 + u];
        }
    }

    float hprev = 0.f;

    for (int s4 = 0; s4 < S_; s4 += 4) {
        #pragma unroll
        for (int ph = 0; ph < 4; ph++) {
            const int s = s4 + ph;
            const int cur = ph & 1;
            const int nxt = cur ^ 1;

            const u64* hp = (const u64*)&sh[cur][g][half * 32];
            u64 ar0 = 0ull, ar1 = 0ull, az0 = 0ull, az1 = 0ull, an0 = 0ull, an1 = 0ull;
            #pragma unroll
            for (int j = 0; j < 16; j += 2) {
                u64 h0 = hp[j], h1 = hp[j + 1];
                ar0 = ffma2(w2r[j], h0, ar0); ar1 = ffma2(w2r[j + 1], h1, ar1);
                az0 = ffma2(w2z[j], h0, az0); az1 = ffma2(w2z[j + 1], h1, az1);
                an0 = ffma2(w2n[j], h0, an0); an1 = ffma2(w2n[j + 1], h1, an1);
            }
            float2 fr = unpack2(fadd2(ar0, ar1));
            float2 fz = unpack2(fadd2(az0, az1));
            float2 fn = unpack2(fadd2(an0, an1));
            float rdot = fr.x + fr.y;
            float zdot = fz.x + fz.y;
            float ndot = fn.x + fn.y;
            rdot += __shfl_xor_sync(0xffffffffu, rdot, 1);
            zdot += __shfl_xor_sync(0xffffffffu, zdot, 1);
            ndot += __shfl_xor_sync(0xffffffffu, ndot, 1);

            if (half == 0) {
                float r = fast_sigmoid(pir[ph] + rdot);
                float z = fast_sigmoid(pii[ph] + zdot);
                float n = fast_tanh(pin[ph] + r * ndot);
                float hn = n + z * (hprev - n);
                hprev = hn;
                sh[nxt][g][u] = hn;
                size_t idx = ((size_t)b * S_ + s) * H_ + u;
                __nv_bfloat16 hb = __float2bfloat16(hn);
                hhi[idx] = hb;
                hlo[idx] = __float2bfloat16(hn - __bfloat162float(hb));
                if (s + 4 < S_) {
                    size_t nb = base + (size_t)(s + 4) * G_;
                    pir[ph] = gx[nb + u];
                    pii[ph] = gx[nb + 64 + u];
                    pin[ph] = gx[nb + 128 + u];
                }
            }
            BARG(barid);
        }
    }
}

// ---------------- fc3 + softmax ---------------------------------------------
__global__ __launch_bounds__(128) void fc3_softmax(
    const float* __restrict__ fc2, const float* __restrict__ W3,
    float* __restrict__ out)
{
    const int b = blockIdx.x;
    const int t = threadIdx.x;
    __shared__ float sa[256];
    __shared__ float slog[C_];
    __shared__ float red[128];

    for (int k = t; k < 256; k += 128) sa[k] = fmaxf(fc2[b * 256 + k], 0.f);
    __syncthreads();

    float acc = 0.f;
    if (t < C_) {
        const float* wr = &W3[t * 256];
        #pragma unroll 8
        for (int k = 0; k < 256; k++) acc += sa[k] * wr[k];
        slog[t] = acc;
    }
    __syncthreads();

    float m = -1e30f;
    for (int k = t; k < C_; k += 128) m = fmaxf(m, slog[k]);
    red[t] = m; __syncthreads();
    for (int st = 64; st > 0; st >>= 1) {
        if (t < st) red[t] = fmaxf(red[t], red[t + st]);
        __syncthreads();
    }
    float mx = red[0];
    __syncthreads();

    float e = 0.f;
    if (t < C_) { e = __expf(slog[t] - mx); slog[t] = e; }
    red[t] = (t < C_) ? e : 0.f; __syncthreads();
    for (int st = 64; st > 0; st >>= 1) {
        if (t < st) red[t] += red[t + st];
        __syncthreads();
    }
    float inv = 1.0f / red[0];
    __syncthreads();

    if (t < C_) out[b * C_ + t] = slog[t] * inv;
}

// ---------------- launch ------------------------------------------------------
extern "C" void kernel_launch(void* const* d_in, const int* in_sizes, int n_in,
                              void* d_out, int out_size)
{
    const float* x     = (const float*)d_in[0];
    const float* W_x2h = (const float*)d_in[1];
    const float* W_h2h = (const float*)d_in[2];
    const float* W1    = (const float*)d_in[3];
    const float* W2    = (const float*)d_in[4];
    const float* W3    = (const float*)d_in[5];
    float* out = (float*)d_out;

    float *gx, *fc1p, *fc1, *fc2;
    __nv_bfloat16 *wxhi, *wxlo, *hhi, *hlo, *w1hi, *w1lo;
    cudaGetSymbolAddress((void**)&gx,   g_gx);
    cudaGetSymbolAddress((void**)&wxhi, g_wxhi);
    cudaGetSymbolAddress((void**)&wxlo, g_wxlo);
    cudaGetSymbolAddress((void**)&hhi,  g_hhi);
    cudaGetSymbolAddress((void**)&hlo,  g_hlo);
    cudaGetSymbolAddress((void**)&w1hi, g_w1hi);
    cudaGetSymbolAddress((void**)&w1lo, g_w1lo);
    cudaGetSymbolAddress((void**)&fc1p, g_fc1p);
    cudaGetSymbolAddress((void**)&fc1,  g_fc1);
    cudaGetSymbolAddress((void**)&fc2,  g_fc2);

    cudaFuncSetAttribute(gx_mma,  cudaFuncAttributeMaxDynamicSharedMemorySize, GX_SMEM);
    cudaFuncSetAttribute(fc1_mma, cudaFuncAttributeMaxDynamicSharedMemorySize, FC1_SMEM);

    // 1) W_x2h -> bf16 hi/lo (tiny)
    cvt_split<<<24, 256>>>(W_x2h, wxhi, wxlo);
    // 2) gx = x @ Wx^T (A converted in-kernel; x read once)
    gx_mma<<<1024, 384, GX_SMEM>>>(x, wxhi, wxlo, gx);
    // 3) GRU scan v3 + fused W1 convert
    gru_scan<<<128, 384>>>(gx, W_h2h, hhi, hlo, W1, w1hi, w1lo);
    // 4) fc1 partials (BM=256, profiled slot) + 5) reduce
    fc1_mma<<<dim3(4, SPLITK), 512, FC1_SMEM>>>(hhi, hlo, w1hi, w1lo, fc1p);
    reduce_fc1<<<128, 256>>>(fc1p, fc1);
    // 6) fc2 = relu(fc1) @ W2^T
    {
        dim3 grid(256 / 64, B_ / 64);
        gemm2<64, 64, 4, 4, true><<<grid, 256>>>(fc1, W2, fc2, B_, 256, 512);
    }
    // 7) logits + softmax
    fc3_softmax<<<B_, 128>>>(fc2, W3, out);
}